// round 11
// baseline (speedup 1.0000x reference)
#include <cuda_runtime.h>
#include <cuda_bf16.h>
#include <cstdint>

#define MM    100000   // simplices
#define KTOT  5        // [x, Ll x, Ll^2 x, Lu x, Lu^2 x]
#define ELLW  48       // ELL row capacity
// ubf slot: per m, 32 groups x 16B; group g = [hi ch4g..4g+3 (8B) | lo (8B)]
#define UBF_SLOT ((size_t)MM * 256)   // uint16 elems per k-slot (512 B/row)

// ---------------- scratch (device globals: no allocations allowed) ----------
__device__ __align__(16) uint16_t g_ubf[(size_t)KTOT * MM * 256];  // 256MB
__device__ __align__(16) uint2    g_wfrag[2 * 20 * 8 * 32];        // B frags, 80KB
__device__ int   g_cnt [2 * MM];
__device__ __align__(16) int2 g_ents[(size_t)2 * MM * ELLW];

// ---------------- helpers ----------------------------------------------------
__device__ __forceinline__ uint32_t smem_u32(const void* p) {
    uint32_t a;
    asm("{ .reg .u64 t; cvta.to.shared.u64 t, %1; cvt.u32.u64 %0, t; }"
        : "=r"(a) : "l"(p));
    return a;
}
__device__ __forceinline__ void cp_async8(uint32_t dst, const void* src, int szr) {
    asm volatile("cp.async.ca.shared.global [%0], [%1], 8, %2;"
                 :: "r"(dst), "l"(src), "r"(szr));
}
#define CP_COMMIT() asm volatile("cp.async.commit_group;" ::: "memory")
#define CP_WAIT1()  asm volatile("cp.async.wait_group 1;" ::: "memory")
#define CP_WAIT0()  asm volatile("cp.async.wait_group 0;" ::: "memory")

__device__ __forceinline__ void ldm_x4(uint32_t* r, uint32_t addr) {
    asm volatile("ldmatrix.sync.aligned.m8n8.x4.shared.b16 {%0,%1,%2,%3}, [%4];"
                 : "=r"(r[0]), "=r"(r[1]), "=r"(r[2]), "=r"(r[3]) : "r"(addr));
}
__device__ __forceinline__ void mma16816(float* c, const uint32_t* a,
                                         uint32_t b0, uint32_t b1) {
    asm volatile("mma.sync.aligned.m16n8k16.row.col.f32.bf16.bf16.f32 "
                 "{%0,%1,%2,%3}, {%4,%5,%6,%7}, {%8,%9}, {%0,%1,%2,%3};"
                 : "+f"(c[0]), "+f"(c[1]), "+f"(c[2]), "+f"(c[3])
                 : "r"(a[0]), "r"(a[1]), "r"(a[2]), "r"(a[3]), "r"(b0), "r"(b1));
}
__device__ __forceinline__ uint16_t bf_bits(__nv_bfloat16 h) {
    return *reinterpret_cast<uint16_t*>(&h);
}
__device__ __forceinline__ float2 bf2f(uint32_t u) {
    __nv_bfloat162 h = *reinterpret_cast<__nv_bfloat162*>(&u);
    return __bfloat1622float2(h);
}
// accumulate v * (hi+lo) for one interleaved uint4 (4 channels)
__device__ __forceinline__ void acc4(float& ax, float& ay, float& az, float& aw,
                                     uint4 g, float v) {
    float2 h01 = bf2f(g.x), h23 = bf2f(g.y);
    float2 l01 = bf2f(g.z), l23 = bf2f(g.w);
    ax += v * (h01.x + l01.x); ay += v * (h01.y + l01.y);
    az += v * (h23.x + l23.x); aw += v * (h23.y + l23.y);
}

// ---------------- 1) transpose x (128, M) -> ubf slot 0 (hi/lo interleave) --
__global__ void transpose_kernel(const float* __restrict__ x) {
    __shared__ float tile[32][33];
    int mBase = blockIdx.x * 32, fBase = blockIdx.y * 32;
    int tx = threadIdx.x, ty = threadIdx.y;
#pragma unroll
    for (int i = 0; i < 32; i += 8)
        tile[ty + i][tx] = x[(size_t)(fBase + ty + i) * MM + mBase + tx];
    __syncthreads();
    uint16_t* ub = g_ubf;
#pragma unroll
    for (int i = 0; i < 32; i += 8) {
        float v = tile[tx][ty + i];
        int m = mBase + ty + i, f = fBase + tx;
        __nv_bfloat16 h = __float2bfloat16_rn(v);
        __nv_bfloat16 l = __float2bfloat16_rn(v - __bfloat162float(h));
        size_t base = (size_t)m * 256 + (size_t)(f >> 2) * 8 + (f & 3);
        ub[base]     = bf_bits(h);     // hi half of group
        ub[base + 4] = bf_bits(l);     // lo half of group
    }
}

// ---------------- ELL build ---------------------------------------------------
__global__ void scatter_ell_kernel(const int* __restrict__ LlI, const int* __restrict__ LuI,
                                   const float* __restrict__ LlV, const float* __restrict__ LuV,
                                   int* __restrict__ cnt, int2* __restrict__ ents, int nnz) {
    int e = blockIdx.x * blockDim.x + threadIdx.x;
    if (e >= 2 * nnz) return;
    int s = (e >= nnz);
    int el = e - s * nnz;
    int r   = s ? LuI[el]       : LlI[el];
    int c   = s ? LuI[el + nnz] : LlI[el + nnz];
    float v = s ? LuV[el]       : LlV[el];
    int idx = atomicAdd(&cnt[s * MM + r], 1);
    if (idx < ELLW)
        ents[(size_t)(s * MM + r) * ELLW + idx] = make_int2(c, __float_as_int(v));
}

// ---------------- 2) dual ELL SpMM: bf16 hi/lo in, bf16 hi/lo out ------------
__global__ void spmm_dual_kernel(const int* __restrict__ cnt, const int2* __restrict__ entsB,
                                 const uint4* __restrict__ in0, const uint4* __restrict__ in1,
                                 uint4* __restrict__ ob0, uint4* __restrict__ ob1) {
    int w = (blockIdx.x * blockDim.x + threadIdx.x) >> 5;
    if (w >= 2 * MM) return;
    int s = (w >= MM);
    int r = w - s * MM;
    int lane = threadIdx.x & 31;
    const uint4* in = s ? in1 : in0;

    int n = __ldg(cnt + s * MM + r);
    n = n < ELLW ? n : ELLW;
    const int2* ents = entsB + (size_t)(s * MM + r) * ELLW;
    int j = 0;
    float ax = 0.f, ay = 0.f, az = 0.f, aw = 0.f;

    for (; n >= 4; n -= 4, j += 4) {
        int2 e0 = __ldg(ents + j);
        int2 e1 = __ldg(ents + j + 1);
        int2 e2 = __ldg(ents + j + 2);
        int2 e3 = __ldg(ents + j + 3);
        uint4 g0 = __ldg(in + (size_t)e0.x * 32 + lane);
        uint4 g1 = __ldg(in + (size_t)e1.x * 32 + lane);
        uint4 g2 = __ldg(in + (size_t)e2.x * 32 + lane);
        uint4 g3 = __ldg(in + (size_t)e3.x * 32 + lane);
        acc4(ax, ay, az, aw, g0, __int_as_float(e0.y));
        acc4(ax, ay, az, aw, g1, __int_as_float(e1.y));
        acc4(ax, ay, az, aw, g2, __int_as_float(e2.y));
        acc4(ax, ay, az, aw, g3, __int_as_float(e3.y));
    }
    for (; n > 0; n--, j++) {
        int2 ev = __ldg(ents + j);
        uint4 g = __ldg(in + (size_t)ev.x * 32 + lane);
        acc4(ax, ay, az, aw, g, __int_as_float(ev.y));
    }

    __nv_bfloat162 h01 = __floats2bfloat162_rn(ax, ay);
    __nv_bfloat162 h23 = __floats2bfloat162_rn(az, aw);
    float2 f01 = __bfloat1622float2(h01);
    float2 f23 = __bfloat1622float2(h23);
    __nv_bfloat162 l01 = __floats2bfloat162_rn(ax - f01.x, ay - f01.y);
    __nv_bfloat162 l23 = __floats2bfloat162_rn(az - f23.x, aw - f23.y);
    uint4 o;
    o.x = *reinterpret_cast<uint32_t*>(&h01);
    o.y = *reinterpret_cast<uint32_t*>(&h23);
    o.z = *reinterpret_cast<uint32_t*>(&l01);
    o.w = *reinterpret_cast<uint32_t*>(&l23);
    (s ? ob1 : ob0)[(size_t)r * 32 + lane] = o;
}

// ---------------- 3) fold theta -> B fragments (mma register order) ---------
__global__ void wprep_kernel(const float* __restrict__ theta, uint2* __restrict__ wfrag) {
    int i = blockIdx.x * blockDim.x + threadIdx.x;
    if (i >= 2 * 20 * 8 * 32) return;
    int lane = i & 31;
    int oc   = (i >> 5) & 7;
    int kk   = (i >> 8) % 20;
    int part = i / 5120;
    int tg = lane & 3, g = lane >> 2;
    int o = oc * 8 + g;
    const int kmap[KTOT] = {0, 1, 2, 4, 5};
    uint16_t bits[4];
#pragma unroll
    for (int e = 0; e < 4; e++) {
        int j = kk * 16 + 2 * tg + (e & 1) + (e >> 1) * 8;
        int kb = j >> 6, c = j & 63;
        float f = theta[(o * 64 + c) * 6 + kmap[kb]];
        if (kb == 0) f += theta[(o * 64 + c) * 6 + 3];
        __nv_bfloat16 h = __float2bfloat16_rn(f);
        if (part == 0) bits[e] = bf_bits(h);
        else           bits[e] = bf_bits(__float2bfloat16_rn(f - __bfloat162float(h)));
    }
    wfrag[i] = make_uint2((uint32_t)bits[0] | ((uint32_t)bits[1] << 16),
                          (uint32_t)bits[2] | ((uint32_t)bits[3] << 16));
}

// ---------------- 4) combine: warp-level bf16 MMA over a slot list ----------
// ns slots (k indices); accum=0: y = D + bias; accum=1: y += D.
#define CMB_THREADS 256
#define SM_WF    0
#define WF_BYTES 81920
#define UB_PLANE 18432                  // 128 rows * 144B (64ch + pad)
#define UB_BYTES (2 * UB_PLANE)         // hi + lo planes
#define SM_U0    WF_BYTES
#define CMB_SMEM_BYTES (WF_BYTES + 2 * UB_BYTES)   // 155648

__global__ __launch_bounds__(CMB_THREADS, 1)
void combine_kernel(const float* __restrict__ bias, float* __restrict__ y,
                    int ns, int sA, int sB, int sC, int accum) {
    extern __shared__ char smem[];
    int t = threadIdx.x;
    int lane = t & 31, w = t >> 5;
    int b = blockIdx.y;
    int mBase = blockIdx.x * 128;

    // stage W fragments (80KB)
    {
        const float4* src = reinterpret_cast<const float4*>(g_wfrag);
        float4* dst = reinterpret_cast<float4*>(smem + SM_WF);
#pragma unroll
        for (int i = t; i < WF_BYTES / 16; i += CMB_THREADS)
            dst[i] = src[i];
    }

    float acc[8][4];
#pragma unroll
    for (int oc = 0; oc < 8; oc++)
#pragma unroll
        for (int e = 0; e < 4; e++) acc[oc][e] = 0.f;

    auto slotOf = [&](int p) { return (p == 0) ? sA : (p == 1) ? sB : sC; };

    auto stage = [&](int slot, int buf) {
        const char* srcb = reinterpret_cast<const char*>(g_ubf + (size_t)slot * UBF_SLOT);
        char* dbase = smem + SM_U0 + buf * UB_BYTES;
#pragma unroll
        for (int jj = 0; jj < 16; jj++) {
            int idx = t + jj * CMB_THREADS;      // 0..4095
            int row = idx >> 5;
            int rem = idx & 31;
            int plane = rem >> 4, i = rem & 15;
            int mm = mBase + row;
            int ok = (mm < MM);
            const char* sp = srcb + (size_t)(ok ? mm : 0) * 512
                             + (b * 16 + i) * 16 + plane * 8;
            uint32_t d = smem_u32(dbase + plane * UB_PLANE + row * 144 + i * 8);
            cp_async8(d, sp, ok ? 8 : 0);
        }
    };

    stage(slotOf(0), 0);
    CP_COMMIT();

    const uint2* wf = reinterpret_cast<const uint2*>(smem + SM_WF);
    int lr = lane & 7;
    int rsel = (lane & 8) ? 8 : 0;
    int csel = (lane & 16) ? 8 : 0;

#pragma unroll 1
    for (int p = 0; p < ns; p++) {
        if (p < ns - 1) { stage(slotOf(p + 1), (p + 1) & 1); CP_COMMIT(); CP_WAIT1(); }
        else            { CP_WAIT0(); }
        __syncthreads();

        int slot = slotOf(p);
        char* hbuf = smem + SM_U0 + (p & 1) * UB_BYTES;
        char* lbuf = hbuf + UB_PLANE;
        int rowA = w * 16 + lr + rsel;
#pragma unroll
        for (int kl = 0; kl < 4; kl++) {
            int colA = kl * 16 + csel;
            uint32_t ah[4], al[4];
            ldm_x4(ah, smem_u32(hbuf + rowA * 144 + colA * 2));
            ldm_x4(al, smem_u32(lbuf + rowA * 144 + colA * 2));
            int kk = slot * 4 + kl;
#pragma unroll
            for (int oc = 0; oc < 8; oc++) {
                uint2 wh = wf[((0 * 20 + kk) * 8 + oc) * 32 + lane];
                uint2 wl = wf[((1 * 20 + kk) * 8 + oc) * 32 + lane];
                mma16816(acc[oc], ah, wh.x, wh.y);
                mma16816(acc[oc], ah, wl.x, wl.y);
                mma16816(acc[oc], al, wh.x, wh.y);
            }
        }
        __syncthreads();
    }

    // epilogue: transpose D through smem -> coalesced y
    float* dout = reinterpret_cast<float*>(smem + SM_U0);   // [64][132]
    int g = lane >> 2, tg = lane & 3;
#pragma unroll
    for (int oc = 0; oc < 8; oc++) {
        int o = oc * 8 + 2 * tg;
        int ml = w * 16 + g;
        dout[o * 132 + ml]           = acc[oc][0];
        dout[(o + 1) * 132 + ml]     = acc[oc][1];
        dout[o * 132 + ml + 8]       = acc[oc][2];
        dout[(o + 1) * 132 + ml + 8] = acc[oc][3];
    }
    __syncthreads();

    int o = t >> 2, q = t & 3;
    float bv = accum ? 0.f : __ldg(bias + o);
    float* yrow = y + ((size_t)b * 64 + o) * MM;
#pragma unroll
    for (int i = 0; i < 8; i++) {
        int c4 = q + i * 4;
        int m = mBase + c4 * 4;
        float4 v = *reinterpret_cast<float4*>(dout + o * 132 + c4 * 4);
        if (m + 3 < MM) {
            if (accum) {
                float4 old = *reinterpret_cast<const float4*>(yrow + m);
                v.x += old.x; v.y += old.y; v.z += old.z; v.w += old.w;
            } else {
                v.x += bv; v.y += bv; v.z += bv; v.w += bv;
            }
            *reinterpret_cast<float4*>(yrow + m) = v;
        } else {
            float vv[4] = {v.x, v.y, v.z, v.w};
#pragma unroll
            for (int e = 0; e < 4; e++)
                if (m + e < MM)
                    yrow[m + e] = accum ? (yrow[m + e] + vv[e]) : (vv[e] + bv);
        }
    }
}

// ---------------- launch ----------------------------------------------------
static cudaStream_t g_side = nullptr;
static cudaEvent_t  g_evFork = nullptr, g_evJoin = nullptr;

extern "C" void kernel_launch(void* const* d_in, const int* in_sizes, int n_in,
                              void* d_out, int out_size) {
    const int*   LlI  = (const int*)  d_in[0];
    const float* LlV  = (const float*)d_in[1];
    const int*   LuI  = (const int*)  d_in[2];
    const float* LuV  = (const float*)d_in[3];
    const float* x    = (const float*)d_in[4];
    const float* th   = (const float*)d_in[5];
    const float* bias = (const float*)d_in[6];
    float*       y    = (float*)d_out;
    int nnz = in_sizes[1];

    if (!g_side) {
        cudaStreamCreateWithFlags(&g_side, cudaStreamNonBlocking);
        cudaEventCreateWithFlags(&g_evFork, cudaEventDisableTiming);
        cudaEventCreateWithFlags(&g_evJoin, cudaEventDisableTiming);
    }

    uint16_t* ubf;
    uint2* wfrag;
    cudaGetSymbolAddress((void**)&ubf,   g_ubf);
    cudaGetSymbolAddress((void**)&wfrag, g_wfrag);

    int  *cnt;
    int2 *ents;
    cudaGetSymbolAddress((void**)&cnt,  g_cnt);
    cudaGetSymbolAddress((void**)&ents, g_ents);

    cudaMemsetAsync(cnt, 0, 2 * MM * sizeof(int));

    int eb2 = (2 * nnz + 255) / 256;
    scatter_ell_kernel<<<eb2, 256>>>(LlI, LuI, LlV, LuV, cnt, ents, nnz);

    transpose_kernel<<<dim3(MM / 32, 4), dim3(32, 8)>>>(x);
    wprep_kernel<<<(2 * 20 * 8 * 32 + 255) / 256, 256>>>(th, wfrag);

    uint4* slot0 = reinterpret_cast<uint4*>(ubf);
    uint4* slot1 = reinterpret_cast<uint4*>(ubf + 1 * UBF_SLOT);
    uint4* slot2 = reinterpret_cast<uint4*>(ubf + 2 * UBF_SLOT);
    uint4* slot3 = reinterpret_cast<uint4*>(ubf + 3 * UBF_SLOT);
    uint4* slot4 = reinterpret_cast<uint4*>(ubf + 4 * UBF_SLOT);

    cudaFuncSetAttribute(combine_kernel,
                         cudaFuncAttributeMaxDynamicSharedMemorySize, CMB_SMEM_BYTES);
    dim3 cgrid((MM + 127) / 128, 2);

    int spmmBlocks = (2 * MM * 32 + 255) / 256;
    // pass A: slots 1,3 = L * slot0
    spmm_dual_kernel<<<spmmBlocks, 256>>>(cnt, ents, slot0, slot0, slot1, slot3);

    // fork: side stream runs combine over k={0,1,3} while main runs spmm pass B
    cudaEventRecord(g_evFork, 0);
    cudaStreamWaitEvent(g_side, g_evFork, 0);
    combine_kernel<<<cgrid, CMB_THREADS, CMB_SMEM_BYTES, g_side>>>(
        bias, y, 3, 0, 1, 3, 0);
    cudaEventRecord(g_evJoin, g_side);

    // pass B: slots 2,4 = L * slots 1,3   (main stream, concurrent with above)
    spmm_dual_kernel<<<spmmBlocks, 256>>>(cnt, ents, slot1, slot3, slot2, slot4);

    // join, then accumulate k={2,4} into y
    cudaStreamWaitEvent(0, g_evJoin, 0);
    combine_kernel<<<cgrid, CMB_THREADS, CMB_SMEM_BYTES>>>(
        bias, y, 2, 2, 4, 0, 1);
}

// round 12
// speedup vs baseline: 1.3132x; 1.3132x over previous
#include <cuda_runtime.h>
#include <cuda_fp16.h>
#include <cstdint>

#define MM    100000   // simplices
#define KTOT  5        // [x, Ll x, Ll^2 x, Lu x, Lu^2 x]
#define ELLW  48       // ELL row capacity
// ubf slot: per m, 128 fp16 channels linear = 256B/row
#define UBF_SLOT ((size_t)MM * 128)   // uint16 elems per k-slot

// ---------------- scratch (device globals: no allocations allowed) ----------
__device__ __align__(16) uint16_t g_ubf[(size_t)KTOT * MM * 128];  // 128MB
__device__ __align__(16) uint2    g_wfrag[2 * 20 * 8 * 32];        // fp16 hi/lo W frags, 80KB
__device__ int   g_cnt [2 * MM];
__device__ __align__(16) int2 g_ents[(size_t)2 * MM * ELLW];

// ---------------- helpers ----------------------------------------------------
__device__ __forceinline__ uint32_t smem_u32(const void* p) {
    uint32_t a;
    asm("{ .reg .u64 t; cvta.to.shared.u64 t, %1; cvt.u32.u64 %0, t; }"
        : "=r"(a) : "l"(p));
    return a;
}
__device__ __forceinline__ void cp_async8(uint32_t dst, const void* src, int szr) {
    asm volatile("cp.async.ca.shared.global [%0], [%1], 8, %2;"
                 :: "r"(dst), "l"(src), "r"(szr));
}
#define CP_COMMIT() asm volatile("cp.async.commit_group;" ::: "memory")
#define CP_WAIT1()  asm volatile("cp.async.wait_group 1;" ::: "memory")
#define CP_WAIT0()  asm volatile("cp.async.wait_group 0;" ::: "memory")

__device__ __forceinline__ void ldm_x4(uint32_t* r, uint32_t addr) {
    asm volatile("ldmatrix.sync.aligned.m8n8.x4.shared.b16 {%0,%1,%2,%3}, [%4];"
                 : "=r"(r[0]), "=r"(r[1]), "=r"(r[2]), "=r"(r[3]) : "r"(addr));
}
__device__ __forceinline__ void mma16816(float* c, const uint32_t* a,
                                         uint32_t b0, uint32_t b1) {
    asm volatile("mma.sync.aligned.m16n8k16.row.col.f32.f16.f16.f32 "
                 "{%0,%1,%2,%3}, {%4,%5,%6,%7}, {%8,%9}, {%0,%1,%2,%3};"
                 : "+f"(c[0]), "+f"(c[1]), "+f"(c[2]), "+f"(c[3])
                 : "r"(a[0]), "r"(a[1]), "r"(a[2]), "r"(a[3]), "r"(b0), "r"(b1));
}
__device__ __forceinline__ uint16_t h_bits(__half h) {
    return *reinterpret_cast<uint16_t*>(&h);
}
__device__ __forceinline__ float2 h2f(uint32_t u) {
    __half2 h = *reinterpret_cast<__half2*>(&u);
    return __half22float2(h);
}
// accumulate v * g for one uint2 (4 fp16 channels)
__device__ __forceinline__ void acc4(float& ax, float& ay, float& az, float& aw,
                                     uint2 g, float v) {
    float2 p01 = h2f(g.x), p23 = h2f(g.y);
    ax += v * p01.x; ay += v * p01.y;
    az += v * p23.x; aw += v * p23.y;
}

// ---------------- 1) transpose x (128, M) -> ubf slot 0 (fp16 linear) -------
__global__ void transpose_kernel(const float* __restrict__ x) {
    __shared__ float tile[32][33];
    int mBase = blockIdx.x * 32, fBase = blockIdx.y * 32;
    int tx = threadIdx.x, ty = threadIdx.y;
#pragma unroll
    for (int i = 0; i < 32; i += 8)
        tile[ty + i][tx] = x[(size_t)(fBase + ty + i) * MM + mBase + tx];
    __syncthreads();
#pragma unroll
    for (int i = 0; i < 32; i += 8) {
        float v = tile[tx][ty + i];
        int m = mBase + ty + i, f = fBase + tx;
        g_ubf[(size_t)m * 128 + f] = h_bits(__float2half_rn(v));
    }
}

// ---------------- ELL build ---------------------------------------------------
__global__ void scatter_ell_kernel(const int* __restrict__ LlI, const int* __restrict__ LuI,
                                   const float* __restrict__ LlV, const float* __restrict__ LuV,
                                   int* __restrict__ cnt, int2* __restrict__ ents, int nnz) {
    int e = blockIdx.x * blockDim.x + threadIdx.x;
    if (e >= 2 * nnz) return;
    int s = (e >= nnz);
    int el = e - s * nnz;
    int r   = s ? LuI[el]       : LlI[el];
    int c   = s ? LuI[el + nnz] : LlI[el + nnz];
    float v = s ? LuV[el]       : LlV[el];
    int idx = atomicAdd(&cnt[s * MM + r], 1);
    if (idx < ELLW)
        ents[(size_t)(s * MM + r) * ELLW + idx] = make_int2(c, __float_as_int(v));
}

// ---------------- 2) dual ELL SpMM: fp16 in, fp16 out, fp32 accumulate -------
__global__ void spmm_dual_kernel(const int* __restrict__ cnt, const int2* __restrict__ entsB,
                                 const uint2* __restrict__ in0, const uint2* __restrict__ in1,
                                 uint2* __restrict__ ob0, uint2* __restrict__ ob1) {
    int w = (blockIdx.x * blockDim.x + threadIdx.x) >> 5;
    if (w >= 2 * MM) return;
    int s = (w >= MM);
    int r = w - s * MM;
    int lane = threadIdx.x & 31;
    const uint2* in = s ? in1 : in0;

    int n = __ldg(cnt + s * MM + r);
    n = n < ELLW ? n : ELLW;
    const int2* ents = entsB + (size_t)(s * MM + r) * ELLW;
    int j = 0;
    float ax = 0.f, ay = 0.f, az = 0.f, aw = 0.f;

    for (; n >= 4; n -= 4, j += 4) {
        int2 e0 = __ldg(ents + j);
        int2 e1 = __ldg(ents + j + 1);
        int2 e2 = __ldg(ents + j + 2);
        int2 e3 = __ldg(ents + j + 3);
        uint2 g0 = __ldg(in + (size_t)e0.x * 32 + lane);
        uint2 g1 = __ldg(in + (size_t)e1.x * 32 + lane);
        uint2 g2 = __ldg(in + (size_t)e2.x * 32 + lane);
        uint2 g3 = __ldg(in + (size_t)e3.x * 32 + lane);
        acc4(ax, ay, az, aw, g0, __int_as_float(e0.y));
        acc4(ax, ay, az, aw, g1, __int_as_float(e1.y));
        acc4(ax, ay, az, aw, g2, __int_as_float(e2.y));
        acc4(ax, ay, az, aw, g3, __int_as_float(e3.y));
    }
    for (; n > 0; n--, j++) {
        int2 ev = __ldg(ents + j);
        uint2 g = __ldg(in + (size_t)ev.x * 32 + lane);
        acc4(ax, ay, az, aw, g, __int_as_float(ev.y));
    }

    __half2 o01 = __floats2half2_rn(ax, ay);
    __half2 o23 = __floats2half2_rn(az, aw);
    uint2 o;
    o.x = *reinterpret_cast<uint32_t*>(&o01);
    o.y = *reinterpret_cast<uint32_t*>(&o23);
    (s ? ob1 : ob0)[(size_t)r * 32 + lane] = o;
}

// ---------------- 3) fold theta -> fp16 hi/lo B fragments -------------------
__global__ void wprep_kernel(const float* __restrict__ theta, uint2* __restrict__ wfrag) {
    int i = blockIdx.x * blockDim.x + threadIdx.x;
    if (i >= 2 * 20 * 8 * 32) return;
    int lane = i & 31;
    int oc   = (i >> 5) & 7;
    int kk   = (i >> 8) % 20;
    int part = i / 5120;
    int tg = lane & 3, g = lane >> 2;
    int o = oc * 8 + g;
    const int kmap[KTOT] = {0, 1, 2, 4, 5};
    uint16_t bits[4];
#pragma unroll
    for (int e = 0; e < 4; e++) {
        int j = kk * 16 + 2 * tg + (e & 1) + (e >> 1) * 8;
        int kb = j >> 6, c = j & 63;
        float f = theta[(o * 64 + c) * 6 + kmap[kb]];
        if (kb == 0) f += theta[(o * 64 + c) * 6 + 3];
        __half h = __float2half_rn(f);
        if (part == 0) bits[e] = h_bits(h);
        else           bits[e] = h_bits(__float2half_rn(f - __half2float(h)));
    }
    wfrag[i] = make_uint2((uint32_t)bits[0] | ((uint32_t)bits[1] << 16),
                          (uint32_t)bits[2] | ((uint32_t)bits[3] << 16));
}

// ---------------- 4) combine: warp-level fp16 MMA (u*wh + u*wl) -------------
// CTA: 256 thr (8 warps), tile 128m x 64o, batch b = blockIdx.y.
#define CMB_THREADS 256
#define SM_WF    0
#define WF_BYTES 81920
#define UB_PLANE 18432                  // 128 rows * 144B (64ch fp16 + pad)
#define SM_U0    WF_BYTES
#define CMB_SMEM_BYTES (WF_BYTES + 2 * UB_PLANE)   // 118784

__global__ __launch_bounds__(CMB_THREADS, 1)
void combine_kernel(const float* __restrict__ bias, float* __restrict__ y) {
    extern __shared__ char smem[];
    int t = threadIdx.x;
    int lane = t & 31, w = t >> 5;
    int b = blockIdx.y;
    int mBase = blockIdx.x * 128;

    // stage W fragments (80KB)
    {
        const float4* src = reinterpret_cast<const float4*>(g_wfrag);
        float4* dst = reinterpret_cast<float4*>(smem + SM_WF);
#pragma unroll
        for (int i = t; i < WF_BYTES / 16; i += CMB_THREADS)
            dst[i] = src[i];
    }

    float acc[8][4];
#pragma unroll
    for (int oc = 0; oc < 8; oc++)
#pragma unroll
        for (int e = 0; e < 4; e++) acc[oc][e] = 0.f;

    // stage k-slot p into buffer p&1: 128 rows x 64 fp16 (batch-b half)
    auto stage = [&](int p, int buf) {
        const char* srcb = reinterpret_cast<const char*>(g_ubf + (size_t)p * UBF_SLOT);
        char* dbase = smem + SM_U0 + buf * UB_PLANE;
#pragma unroll
        for (int jj = 0; jj < 8; jj++) {
            int idx = t + jj * CMB_THREADS;      // 0..2047
            int row = idx >> 4;
            int i   = idx & 15;                  // 8B chunk in 128B
            int mm = mBase + row;
            int ok = (mm < MM);
            const char* sp = srcb + (size_t)(ok ? mm : 0) * 256 + b * 128 + i * 8;
            uint32_t d = smem_u32(dbase + row * 144 + i * 8);
            cp_async8(d, sp, ok ? 8 : 0);
        }
    };

    stage(0, 0);
    CP_COMMIT();

    const uint2* wf = reinterpret_cast<const uint2*>(smem + SM_WF);
    int lr = lane & 7;
    int rsel = (lane & 8) ? 8 : 0;
    int csel = (lane & 16) ? 8 : 0;

#pragma unroll 1
    for (int p = 0; p < KTOT; p++) {
        if (p < KTOT - 1) { stage(p + 1, (p + 1) & 1); CP_COMMIT(); CP_WAIT1(); }
        else              { CP_WAIT0(); }
        __syncthreads();

        char* ubuf = smem + SM_U0 + (p & 1) * UB_PLANE;
        int rowA = w * 16 + lr + rsel;
#pragma unroll
        for (int kl = 0; kl < 4; kl++) {
            int colA = kl * 16 + csel;
            uint32_t a[4];
            ldm_x4(a, smem_u32(ubuf + rowA * 144 + colA * 2));
            int kk = p * 4 + kl;
#pragma unroll
            for (int oc = 0; oc < 8; oc++) {
                uint2 wh = wf[((0 * 20 + kk) * 8 + oc) * 32 + lane];
                uint2 wl = wf[((1 * 20 + kk) * 8 + oc) * 32 + lane];
                mma16816(acc[oc], a, wh.x, wh.y);
                mma16816(acc[oc], a, wl.x, wl.y);
            }
        }
        __syncthreads();
    }

    // epilogue: transpose D through smem -> coalesced y
    float* dout = reinterpret_cast<float*>(smem + SM_U0);   // [64][132] = 33792B
    int g = lane >> 2, tg = lane & 3;
#pragma unroll
    for (int oc = 0; oc < 8; oc++) {
        int o = oc * 8 + 2 * tg;
        int ml = w * 16 + g;
        dout[o * 132 + ml]           = acc[oc][0];
        dout[(o + 1) * 132 + ml]     = acc[oc][1];
        dout[o * 132 + ml + 8]       = acc[oc][2];
        dout[(o + 1) * 132 + ml + 8] = acc[oc][3];
    }
    __syncthreads();

    int o = t >> 2, q = t & 3;
    float bv = __ldg(bias + o);
    float* yrow = y + ((size_t)b * 64 + o) * MM;
#pragma unroll
    for (int i = 0; i < 8; i++) {
        int c4 = q + i * 4;
        int m = mBase + c4 * 4;
        float4 v = *reinterpret_cast<float4*>(dout + o * 132 + c4 * 4);
        v.x += bv; v.y += bv; v.z += bv; v.w += bv;
        if (m + 3 < MM) {
            *reinterpret_cast<float4*>(yrow + m) = v;
        } else {
            if (m     < MM) yrow[m]     = v.x;
            if (m + 1 < MM) yrow[m + 1] = v.y;
            if (m + 2 < MM) yrow[m + 2] = v.z;
            if (m + 3 < MM) yrow[m + 3] = v.w;
        }
    }
}

// ---------------- launch (serial, round-10 structure) ------------------------
extern "C" void kernel_launch(void* const* d_in, const int* in_sizes, int n_in,
                              void* d_out, int out_size) {
    const int*   LlI  = (const int*)  d_in[0];
    const float* LlV  = (const float*)d_in[1];
    const int*   LuI  = (const int*)  d_in[2];
    const float* LuV  = (const float*)d_in[3];
    const float* x    = (const float*)d_in[4];
    const float* th   = (const float*)d_in[5];
    const float* bias = (const float*)d_in[6];
    float*       y    = (float*)d_out;
    int nnz = in_sizes[1];

    uint16_t* ubf;
    uint2* wfrag;
    cudaGetSymbolAddress((void**)&ubf,   g_ubf);
    cudaGetSymbolAddress((void**)&wfrag, g_wfrag);

    int  *cnt;
    int2 *ents;
    cudaGetSymbolAddress((void**)&cnt,  g_cnt);
    cudaGetSymbolAddress((void**)&ents, g_ents);

    cudaMemsetAsync(cnt, 0, 2 * MM * sizeof(int));

    int eb2 = (2 * nnz + 255) / 256;
    scatter_ell_kernel<<<eb2, 256>>>(LlI, LuI, LlV, LuV, cnt, ents, nnz);

    transpose_kernel<<<dim3(MM / 32, 4), dim3(32, 8)>>>(x);
    wprep_kernel<<<(2 * 20 * 8 * 32 + 255) / 256, 256>>>(th, wfrag);

    uint2* slot0 = reinterpret_cast<uint2*>(ubf);
    uint2* slot1 = reinterpret_cast<uint2*>(ubf + 1 * UBF_SLOT);
    uint2* slot2 = reinterpret_cast<uint2*>(ubf + 2 * UBF_SLOT);
    uint2* slot3 = reinterpret_cast<uint2*>(ubf + 3 * UBF_SLOT);
    uint2* slot4 = reinterpret_cast<uint2*>(ubf + 4 * UBF_SLOT);

    int spmmBlocks = (2 * MM * 32 + 255) / 256;
    spmm_dual_kernel<<<spmmBlocks, 256>>>(cnt, ents, slot0, slot0, slot1, slot3);
    spmm_dual_kernel<<<spmmBlocks, 256>>>(cnt, ents, slot1, slot3, slot2, slot4);

    cudaFuncSetAttribute(combine_kernel,
                         cudaFuncAttributeMaxDynamicSharedMemorySize, CMB_SMEM_BYTES);
    combine_kernel<<<dim3((MM + 127) / 128, 2), CMB_THREADS, CMB_SMEM_BYTES>>>(bias, y);
}

// round 13
// speedup vs baseline: 1.3333x; 1.0153x over previous
#include <cuda_runtime.h>
#include <cuda_fp16.h>
#include <cstdint>

#define MM    100000   // simplices
#define KTOT  5        // [x, Ll x, Ll^2 x, Lu x, Lu^2 x]
#define ELLW  48       // ELL row capacity
// ubf slot: per m, 128 fp16 channels linear = 256B/row
#define UBF_SLOT ((size_t)MM * 128)   // uint16 elems per k-slot

// ---------------- scratch (device globals: no allocations allowed) ----------
__device__ __align__(16) uint16_t g_ubf[(size_t)KTOT * MM * 128];  // 128MB
__device__ __align__(16) uint2    g_wfrag[2 * 20 * 8 * 32];        // fp16 hi/lo W frags
__device__ int   g_cnt [2 * MM];
__device__ __align__(16) int2 g_ents[(size_t)2 * MM * ELLW];

// ---------------- helpers ----------------------------------------------------
__device__ __forceinline__ uint32_t smem_u32(const void* p) {
    uint32_t a;
    asm("{ .reg .u64 t; cvta.to.shared.u64 t, %1; cvt.u32.u64 %0, t; }"
        : "=r"(a) : "l"(p));
    return a;
}
__device__ __forceinline__ void cp_async8(uint32_t dst, const void* src, int szr) {
    asm volatile("cp.async.ca.shared.global [%0], [%1], 8, %2;"
                 :: "r"(dst), "l"(src), "r"(szr));
}
#define CP_COMMIT() asm volatile("cp.async.commit_group;" ::: "memory")
#define CP_WAIT1()  asm volatile("cp.async.wait_group 1;" ::: "memory")
#define CP_WAIT0()  asm volatile("cp.async.wait_group 0;" ::: "memory")

__device__ __forceinline__ void ldm_x4(uint32_t* r, uint32_t addr) {
    asm volatile("ldmatrix.sync.aligned.m8n8.x4.shared.b16 {%0,%1,%2,%3}, [%4];"
                 : "=r"(r[0]), "=r"(r[1]), "=r"(r[2]), "=r"(r[3]) : "r"(addr));
}
__device__ __forceinline__ void mma16816(float* c, const uint32_t* a,
                                         uint32_t b0, uint32_t b1) {
    asm volatile("mma.sync.aligned.m16n8k16.row.col.f32.f16.f16.f32 "
                 "{%0,%1,%2,%3}, {%4,%5,%6,%7}, {%8,%9}, {%0,%1,%2,%3};"
                 : "+f"(c[0]), "+f"(c[1]), "+f"(c[2]), "+f"(c[3])
                 : "r"(a[0]), "r"(a[1]), "r"(a[2]), "r"(a[3]), "r"(b0), "r"(b1));
}
__device__ __forceinline__ uint16_t h_bits(__half h) {
    return *reinterpret_cast<uint16_t*>(&h);
}
__device__ __forceinline__ float2 h2f(uint32_t u) {
    __half2 h = *reinterpret_cast<__half2*>(&u);
    return __half22float2(h);
}
__device__ __forceinline__ void acc4(float& ax, float& ay, float& az, float& aw,
                                     uint2 g, float v) {
    float2 p01 = h2f(g.x), p23 = h2f(g.y);
    ax += v * p01.x; ay += v * p01.y;
    az += v * p23.x; aw += v * p23.y;
}

// ---------------- 1) transpose x (128, M) -> ubf slot 0 (fp16 linear) -------
__global__ void transpose_kernel(const float* __restrict__ x) {
    __shared__ float tile[32][33];
    int mBase = blockIdx.x * 32, fBase = blockIdx.y * 32;
    int tx = threadIdx.x, ty = threadIdx.y;
#pragma unroll
    for (int i = 0; i < 32; i += 8)
        tile[ty + i][tx] = x[(size_t)(fBase + ty + i) * MM + mBase + tx];
    __syncthreads();
#pragma unroll
    for (int i = 0; i < 32; i += 8) {
        float v = tile[tx][ty + i];
        int m = mBase + ty + i, f = fBase + tx;
        g_ubf[(size_t)m * 128 + f] = h_bits(__float2half_rn(v));
    }
}

// ---------------- ELL build ---------------------------------------------------
__global__ void scatter_ell_kernel(const int* __restrict__ LlI, const int* __restrict__ LuI,
                                   const float* __restrict__ LlV, const float* __restrict__ LuV,
                                   int* __restrict__ cnt, int2* __restrict__ ents, int nnz) {
    int e = blockIdx.x * blockDim.x + threadIdx.x;
    if (e >= 2 * nnz) return;
    int s = (e >= nnz);
    int el = e - s * nnz;
    int r   = s ? LuI[el]       : LlI[el];
    int c   = s ? LuI[el + nnz] : LlI[el + nnz];
    float v = s ? LuV[el]       : LlV[el];
    int idx = atomicAdd(&cnt[s * MM + r], 1);
    if (idx < ELLW)
        ents[(size_t)(s * MM + r) * ELLW + idx] = make_int2(c, __float_as_int(v));
}

// ---------------- 2) dual ELL SpMM v2: MLP-8 batches, lane-parallel entries --
__global__ void spmm_dual_kernel(const int* __restrict__ cnt, const int2* __restrict__ entsB,
                                 const uint2* __restrict__ in0, const uint2* __restrict__ in1,
                                 uint2* __restrict__ ob0, uint2* __restrict__ ob1) {
    int w = (blockIdx.x * blockDim.x + threadIdx.x) >> 5;
    if (w >= 2 * MM) return;
    int s = (w >= MM);
    int r = w - s * MM;
    int lane = threadIdx.x & 31;
    const uint2* in = s ? in1 : in0;

    int n = __ldg(cnt + s * MM + r);
    n = n < ELLW ? n : ELLW;
    const int2* ents = entsB + (size_t)(s * MM + r) * ELLW;
    float ax = 0.f, ay = 0.f, az = 0.f, aw = 0.f;

    for (int base = 0; base < n; base += 8) {
        int take = n - base; take = take < 8 ? take : 8;
        // lane-parallel entry fetch: lanes 0..7 load 8 entries in one LDG
        int li = lane & 7;
        int2 my = __ldg(ents + base + (li < take ? li : 0));
        // distribute + issue all 8 gathers back-to-back (MLP-8)
        uint2 g[8];
        float v[8];
#pragma unroll
        for (int i = 0; i < 8; i++) {
            int col  = __shfl_sync(0xffffffffu, my.x, i);
            int vbit = __shfl_sync(0xffffffffu, my.y, i);
            v[i] = (i < take) ? __int_as_float(vbit) : 0.f;
            g[i] = __ldg(in + (size_t)col * 32 + lane);
        }
#pragma unroll
        for (int i = 0; i < 8; i++)
            acc4(ax, ay, az, aw, g[i], v[i]);
    }

    __half2 o01 = __floats2half2_rn(ax, ay);
    __half2 o23 = __floats2half2_rn(az, aw);
    uint2 o;
    o.x = *reinterpret_cast<uint32_t*>(&o01);
    o.y = *reinterpret_cast<uint32_t*>(&o23);
    (s ? ob1 : ob0)[(size_t)r * 32 + lane] = o;
}

// ---------------- 3) fold theta -> fp16 hi/lo B fragments -------------------
__global__ void wprep_kernel(const float* __restrict__ theta, uint2* __restrict__ wfrag) {
    int i = blockIdx.x * blockDim.x + threadIdx.x;
    if (i >= 2 * 20 * 8 * 32) return;
    int lane = i & 31;
    int oc   = (i >> 5) & 7;
    int kk   = (i >> 8) % 20;
    int part = i / 5120;
    int tg = lane & 3, g = lane >> 2;
    int o = oc * 8 + g;
    const int kmap[KTOT] = {0, 1, 2, 4, 5};
    uint16_t bits[4];
#pragma unroll
    for (int e = 0; e < 4; e++) {
        int j = kk * 16 + 2 * tg + (e & 1) + (e >> 1) * 8;
        int kb = j >> 6, c = j & 63;
        float f = theta[(o * 64 + c) * 6 + kmap[kb]];
        if (kb == 0) f += theta[(o * 64 + c) * 6 + 3];
        __half h = __float2half_rn(f);
        if (part == 0) bits[e] = h_bits(h);
        else           bits[e] = h_bits(__float2half_rn(f - __half2float(h)));
    }
    wfrag[i] = make_uint2((uint32_t)bits[0] | ((uint32_t)bits[1] << 16),
                          (uint32_t)bits[2] | ((uint32_t)bits[3] << 16));
}

// ---------------- 4) combine: warp-level fp16 MMA (u*wh + u*wl) -------------
#define CMB_THREADS 256
#define SM_WF    0
#define WF_BYTES 81920
#define UB_PLANE 18432                  // 128 rows * 144B (64ch fp16 + pad)
#define SM_U0    WF_BYTES
#define CMB_SMEM_BYTES (WF_BYTES + 2 * UB_PLANE)   // 118784

__global__ __launch_bounds__(CMB_THREADS, 1)
void combine_kernel(const float* __restrict__ bias, float* __restrict__ y) {
    extern __shared__ char smem[];
    int t = threadIdx.x;
    int lane = t & 31, w = t >> 5;
    int b = blockIdx.y;
    int mBase = blockIdx.x * 128;

    {
        const float4* src = reinterpret_cast<const float4*>(g_wfrag);
        float4* dst = reinterpret_cast<float4*>(smem + SM_WF);
#pragma unroll
        for (int i = t; i < WF_BYTES / 16; i += CMB_THREADS)
            dst[i] = src[i];
    }

    float acc[8][4];
#pragma unroll
    for (int oc = 0; oc < 8; oc++)
#pragma unroll
        for (int e = 0; e < 4; e++) acc[oc][e] = 0.f;

    auto stage = [&](int p, int buf) {
        const char* srcb = reinterpret_cast<const char*>(g_ubf + (size_t)p * UBF_SLOT);
        char* dbase = smem + SM_U0 + buf * UB_PLANE;
#pragma unroll
        for (int jj = 0; jj < 8; jj++) {
            int idx = t + jj * CMB_THREADS;      // 0..2047
            int row = idx >> 4;
            int i   = idx & 15;
            int mm = mBase + row;
            int ok = (mm < MM);
            const char* sp = srcb + (size_t)(ok ? mm : 0) * 256 + b * 128 + i * 8;
            uint32_t d = smem_u32(dbase + row * 144 + i * 8);
            cp_async8(d, sp, ok ? 8 : 0);
        }
    };

    stage(0, 0);
    CP_COMMIT();

    const uint2* wf = reinterpret_cast<const uint2*>(smem + SM_WF);
    int lr = lane & 7;
    int rsel = (lane & 8) ? 8 : 0;
    int csel = (lane & 16) ? 8 : 0;

#pragma unroll 1
    for (int p = 0; p < KTOT; p++) {
        if (p < KTOT - 1) { stage(p + 1, (p + 1) & 1); CP_COMMIT(); CP_WAIT1(); }
        else              { CP_WAIT0(); }
        __syncthreads();

        char* ubuf = smem + SM_U0 + (p & 1) * UB_PLANE;
        int rowA = w * 16 + lr + rsel;
#pragma unroll
        for (int kl = 0; kl < 4; kl++) {
            int colA = kl * 16 + csel;
            uint32_t a[4];
            ldm_x4(a, smem_u32(ubuf + rowA * 144 + colA * 2));
            int kk = p * 4 + kl;
#pragma unroll
            for (int oc = 0; oc < 8; oc++) {
                uint2 wh = wf[((0 * 20 + kk) * 8 + oc) * 32 + lane];
                uint2 wl = wf[((1 * 20 + kk) * 8 + oc) * 32 + lane];
                mma16816(acc[oc], a, wh.x, wh.y);
                mma16816(acc[oc], a, wl.x, wl.y);
            }
        }
        __syncthreads();
    }

    float* dout = reinterpret_cast<float*>(smem + SM_U0);   // [64][132]
    int g = lane >> 2, tg = lane & 3;
#pragma unroll
    for (int oc = 0; oc < 8; oc++) {
        int o = oc * 8 + 2 * tg;
        int ml = w * 16 + g;
        dout[o * 132 + ml]           = acc[oc][0];
        dout[(o + 1) * 132 + ml]     = acc[oc][1];
        dout[o * 132 + ml + 8]       = acc[oc][2];
        dout[(o + 1) * 132 + ml + 8] = acc[oc][3];
    }
    __syncthreads();

    int o = t >> 2, q = t & 3;
    float bv = __ldg(bias + o);
    float* yrow = y + ((size_t)b * 64 + o) * MM;
#pragma unroll
    for (int i = 0; i < 8; i++) {
        int c4 = q + i * 4;
        int m = mBase + c4 * 4;
        float4 v = *reinterpret_cast<float4*>(dout + o * 132 + c4 * 4);
        v.x += bv; v.y += bv; v.z += bv; v.w += bv;
        if (m + 3 < MM) {
            *reinterpret_cast<float4*>(yrow + m) = v;
        } else {
            if (m     < MM) yrow[m]     = v.x;
            if (m + 1 < MM) yrow[m + 1] = v.y;
            if (m + 2 < MM) yrow[m + 2] = v.z;
            if (m + 3 < MM) yrow[m + 3] = v.w;
        }
    }
}

// ---------------- launch ------------------------------------------------------
extern "C" void kernel_launch(void* const* d_in, const int* in_sizes, int n_in,
                              void* d_out, int out_size) {
    const int*   LlI  = (const int*)  d_in[0];
    const float* LlV  = (const float*)d_in[1];
    const int*   LuI  = (const int*)  d_in[2];
    const float* LuV  = (const float*)d_in[3];
    const float* x    = (const float*)d_in[4];
    const float* th   = (const float*)d_in[5];
    const float* bias = (const float*)d_in[6];
    float*       y    = (float*)d_out;
    int nnz = in_sizes[1];

    uint16_t* ubf;
    uint2* wfrag;
    cudaGetSymbolAddress((void**)&ubf,   g_ubf);
    cudaGetSymbolAddress((void**)&wfrag, g_wfrag);

    int  *cnt;
    int2 *ents;
    cudaGetSymbolAddress((void**)&cnt,  g_cnt);
    cudaGetSymbolAddress((void**)&ents, g_ents);

    cudaMemsetAsync(cnt, 0, 2 * MM * sizeof(int));

    int eb2 = (2 * nnz + 255) / 256;
    scatter_ell_kernel<<<eb2, 256>>>(LlI, LuI, LlV, LuV, cnt, ents, nnz);

    transpose_kernel<<<dim3(MM / 32, 4), dim3(32, 8)>>>(x);
    wprep_kernel<<<(2 * 20 * 8 * 32 + 255) / 256, 256>>>(th, wfrag);

    uint2* slot0 = reinterpret_cast<uint2*>(ubf);
    uint2* slot1 = reinterpret_cast<uint2*>(ubf + 1 * UBF_SLOT);
    uint2* slot2 = reinterpret_cast<uint2*>(ubf + 2 * UBF_SLOT);
    uint2* slot3 = reinterpret_cast<uint2*>(ubf + 3 * UBF_SLOT);
    uint2* slot4 = reinterpret_cast<uint2*>(ubf + 4 * UBF_SLOT);

    int spmmBlocks = (2 * MM * 32 + 255) / 256;
    spmm_dual_kernel<<<spmmBlocks, 256>>>(cnt, ents, slot0, slot0, slot1, slot3);
    spmm_dual_kernel<<<spmmBlocks, 256>>>(cnt, ents, slot1, slot3, slot2, slot4);

    cudaFuncSetAttribute(combine_kernel,
                         cudaFuncAttributeMaxDynamicSharedMemorySize, CMB_SMEM_BYTES);
    combine_kernel<<<dim3((MM + 127) / 128, 2), CMB_THREADS, CMB_SMEM_BYTES>>>(bias, y);
}

// round 14
// speedup vs baseline: 1.4372x; 1.0780x over previous
#include <cuda_runtime.h>
#include <cuda_fp16.h>
#include <cstdint>

#define MM    100000   // simplices
#define KTOT  5        // [x, Ll x, Ll^2 x, Lu x, Lu^2 x]
#define ELLW  32       // ELL row capacity (Poisson(8) tail @32 ~ 1e-11)
// ubf slot: per m, 128 fp16 channels linear = 256B/row
#define UBF_SLOT ((size_t)MM * 128)   // uint16 elems per k-slot

// ---------------- scratch (device globals: no allocations allowed) ----------
__device__ __align__(16) uint16_t g_ubf[(size_t)KTOT * MM * 128];  // 128MB
__device__ __align__(16) uint2    g_wfrag[2 * 20 * 8 * 32];        // fp16 hi/lo W frags
__device__ int   g_cnt [2 * MM];
__device__ __align__(16) int2 g_ents[(size_t)2 * MM * ELLW];

// ---------------- helpers ----------------------------------------------------
__device__ __forceinline__ uint32_t smem_u32(const void* p) {
    uint32_t a;
    asm("{ .reg .u64 t; cvta.to.shared.u64 t, %1; cvt.u32.u64 %0, t; }"
        : "=r"(a) : "l"(p));
    return a;
}
__device__ __forceinline__ void cp_async8(uint32_t dst, const void* src, int szr) {
    asm volatile("cp.async.ca.shared.global [%0], [%1], 8, %2;"
                 :: "r"(dst), "l"(src), "r"(szr));
}
#define CP_COMMIT() asm volatile("cp.async.commit_group;" ::: "memory")
#define CP_WAIT1()  asm volatile("cp.async.wait_group 1;" ::: "memory")
#define CP_WAIT0()  asm volatile("cp.async.wait_group 0;" ::: "memory")

__device__ __forceinline__ void ldm_x4(uint32_t* r, uint32_t addr) {
    asm volatile("ldmatrix.sync.aligned.m8n8.x4.shared.b16 {%0,%1,%2,%3}, [%4];"
                 : "=r"(r[0]), "=r"(r[1]), "=r"(r[2]), "=r"(r[3]) : "r"(addr));
}
__device__ __forceinline__ void mma16816(float* c, const uint32_t* a,
                                         uint32_t b0, uint32_t b1) {
    asm volatile("mma.sync.aligned.m16n8k16.row.col.f32.f16.f16.f32 "
                 "{%0,%1,%2,%3}, {%4,%5,%6,%7}, {%8,%9}, {%0,%1,%2,%3};"
                 : "+f"(c[0]), "+f"(c[1]), "+f"(c[2]), "+f"(c[3])
                 : "r"(a[0]), "r"(a[1]), "r"(a[2]), "r"(a[3]), "r"(b0), "r"(b1));
}
__device__ __forceinline__ uint16_t h_bits(__half h) {
    return *reinterpret_cast<uint16_t*>(&h);
}
__device__ __forceinline__ float2 h2f(uint32_t u) {
    __half2 h = *reinterpret_cast<__half2*>(&u);
    return __half22float2(h);
}

// ---------------- 1) transpose x (128, M) -> ubf slot 0 (fp16 linear) -------
__global__ void transpose_kernel(const float* __restrict__ x) {
    __shared__ float tile[32][33];
    int mBase = blockIdx.x * 32, fBase = blockIdx.y * 32;
    int tx = threadIdx.x, ty = threadIdx.y;
#pragma unroll
    for (int i = 0; i < 32; i += 8)
        tile[ty + i][tx] = x[(size_t)(fBase + ty + i) * MM + mBase + tx];
    __syncthreads();
#pragma unroll
    for (int i = 0; i < 32; i += 8) {
        float v = tile[tx][ty + i];
        int m = mBase + ty + i, f = fBase + tx;
        g_ubf[(size_t)m * 128 + f] = h_bits(__float2half_rn(v));
    }
}

// ---------------- ELL build ---------------------------------------------------
__global__ void scatter_ell_kernel(const int* __restrict__ LlI, const int* __restrict__ LuI,
                                   const float* __restrict__ LlV, const float* __restrict__ LuV,
                                   int* __restrict__ cnt, int2* __restrict__ ents, int nnz) {
    int e = blockIdx.x * blockDim.x + threadIdx.x;
    if (e >= 2 * nnz) return;
    int s = (e >= nnz);
    int el = e - s * nnz;
    int r   = s ? LuI[el]       : LlI[el];
    int c   = s ? LuI[el + nnz] : LlI[el + nnz];
    float v = s ? LuV[el]       : LlV[el];
    int idx = atomicAdd(&cnt[s * MM + r], 1);
    if (idx < ELLW)
        ents[(size_t)(s * MM + r) * ELLW + idx] = make_int2(c, __float_as_int(v));
}

// ---------------- 2) dual ELL SpMM v3: 2 rows per warp (half-warp rows) ------
// Warp w handles row w of BOTH matrices: lanes 0-15 matrix 0, lanes 16-31
// matrix 1. Row = 16 uint4 (256B fp16). One warp LDG serves both halves.
__global__ __launch_bounds__(256)
void spmm_dual_kernel(const int* __restrict__ cnt, const int2* __restrict__ entsB,
                      const uint4* __restrict__ in0, const uint4* __restrict__ in1,
                      uint4* __restrict__ ob0, uint4* __restrict__ ob1) {
    int w = (blockIdx.x * blockDim.x + threadIdx.x) >> 5;   // row id
    if (w >= MM) return;
    int lane = threadIdx.x & 31;
    int hs = lane >> 4;          // matrix select for this half-warp
    int hl = lane & 15;          // uint4 index within 256B row
    const uint4* in = hs ? in1 : in0;

    int n = __ldg(cnt + hs * MM + w);
    n = n < ELLW ? n : ELLW;
    int noth = __shfl_xor_sync(0xffffffffu, n, 16);
    int nmax = n > noth ? n : noth;
    const int2* ents = entsB + (size_t)(hs * MM + w) * ELLW;

    float acc[8];
#pragma unroll
    for (int i = 0; i < 8; i++) acc[i] = 0.f;

    for (int base = 0; base < nmax; base += 8) {
        int take = n - base;
        take = take < 0 ? 0 : (take > 8 ? 8 : take);
        // lanes 0-7 load matrix-0 entries, lanes 16-23 matrix-1 entries;
        // lanes 8-15/24-31 load duplicates (merged in L1). base+7 <= 31 < ELLW.
        int2 my = __ldg(ents + base + (hl & 7));
        uint4 g[8];
        float v[8];
#pragma unroll
        for (int i = 0; i < 8; i++) {
            int src  = (lane & 16) + i;                     // segmented shfl
            int col  = __shfl_sync(0xffffffffu, my.x, src);
            int vbit = __shfl_sync(0xffffffffu, my.y, src);
            bool ok = (i < take);
            v[i] = ok ? __int_as_float(vbit) : 0.f;
            col  = ok ? col : 0;
            g[i] = __ldg(in + (size_t)col * 16 + hl);       // MLP-8, 2 rows/warp
        }
#pragma unroll
        for (int i = 0; i < 8; i++) {
            float2 a0 = h2f(g[i].x), a1 = h2f(g[i].y);
            float2 a2 = h2f(g[i].z), a3 = h2f(g[i].w);
            acc[0] += v[i] * a0.x; acc[1] += v[i] * a0.y;
            acc[2] += v[i] * a1.x; acc[3] += v[i] * a1.y;
            acc[4] += v[i] * a2.x; acc[5] += v[i] * a2.y;
            acc[6] += v[i] * a3.x; acc[7] += v[i] * a3.y;
        }
    }

    __half2 o0 = __floats2half2_rn(acc[0], acc[1]);
    __half2 o1 = __floats2half2_rn(acc[2], acc[3]);
    __half2 o2 = __floats2half2_rn(acc[4], acc[5]);
    __half2 o3 = __floats2half2_rn(acc[6], acc[7]);
    uint4 o;
    o.x = *reinterpret_cast<uint32_t*>(&o0);
    o.y = *reinterpret_cast<uint32_t*>(&o1);
    o.z = *reinterpret_cast<uint32_t*>(&o2);
    o.w = *reinterpret_cast<uint32_t*>(&o3);
    (hs ? ob1 : ob0)[(size_t)w * 16 + hl] = o;
}

// ---------------- 3) fold theta -> fp16 hi/lo B fragments -------------------
__global__ void wprep_kernel(const float* __restrict__ theta, uint2* __restrict__ wfrag) {
    int i = blockIdx.x * blockDim.x + threadIdx.x;
    if (i >= 2 * 20 * 8 * 32) return;
    int lane = i & 31;
    int oc   = (i >> 5) & 7;
    int kk   = (i >> 8) % 20;
    int part = i / 5120;
    int tg = lane & 3, g = lane >> 2;
    int o = oc * 8 + g;
    const int kmap[KTOT] = {0, 1, 2, 4, 5};
    uint16_t bits[4];
#pragma unroll
    for (int e = 0; e < 4; e++) {
        int j = kk * 16 + 2 * tg + (e & 1) + (e >> 1) * 8;
        int kb = j >> 6, c = j & 63;
        float f = theta[(o * 64 + c) * 6 + kmap[kb]];
        if (kb == 0) f += theta[(o * 64 + c) * 6 + 3];
        __half h = __float2half_rn(f);
        if (part == 0) bits[e] = h_bits(h);
        else           bits[e] = h_bits(__float2half_rn(f - __half2float(h)));
    }
    wfrag[i] = make_uint2((uint32_t)bits[0] | ((uint32_t)bits[1] << 16),
                          (uint32_t)bits[2] | ((uint32_t)bits[3] << 16));
}

// ---------------- 4) combine: warp-level fp16 MMA (u*wh + u*wl) -------------
#define CMB_THREADS 256
#define SM_WF    0
#define WF_BYTES 81920
#define UB_PLANE 18432                  // 128 rows * 144B (64ch fp16 + pad)
#define SM_U0    WF_BYTES
#define CMB_SMEM_BYTES (WF_BYTES + 2 * UB_PLANE)   // 118784

__global__ __launch_bounds__(CMB_THREADS, 1)
void combine_kernel(const float* __restrict__ bias, float* __restrict__ y) {
    extern __shared__ char smem[];
    int t = threadIdx.x;
    int lane = t & 31, w = t >> 5;
    int b = blockIdx.y;
    int mBase = blockIdx.x * 128;

    {
        const float4* src = reinterpret_cast<const float4*>(g_wfrag);
        float4* dst = reinterpret_cast<float4*>(smem + SM_WF);
#pragma unroll
        for (int i = t; i < WF_BYTES / 16; i += CMB_THREADS)
            dst[i] = src[i];
    }

    float acc[8][4];
#pragma unroll
    for (int oc = 0; oc < 8; oc++)
#pragma unroll
        for (int e = 0; e < 4; e++) acc[oc][e] = 0.f;

    auto stage = [&](int p, int buf) {
        const char* srcb = reinterpret_cast<const char*>(g_ubf + (size_t)p * UBF_SLOT);
        char* dbase = smem + SM_U0 + buf * UB_PLANE;
#pragma unroll
        for (int jj = 0; jj < 8; jj++) {
            int idx = t + jj * CMB_THREADS;      // 0..2047
            int row = idx >> 4;
            int i   = idx & 15;
            int mm = mBase + row;
            int ok = (mm < MM);
            const char* sp = srcb + (size_t)(ok ? mm : 0) * 256 + b * 128 + i * 8;
            uint32_t d = smem_u32(dbase + row * 144 + i * 8);
            cp_async8(d, sp, ok ? 8 : 0);
        }
    };

    stage(0, 0);
    CP_COMMIT();

    const uint2* wf = reinterpret_cast<const uint2*>(smem + SM_WF);
    int lr = lane & 7;
    int rsel = (lane & 8) ? 8 : 0;
    int csel = (lane & 16) ? 8 : 0;

#pragma unroll 1
    for (int p = 0; p < KTOT; p++) {
        if (p < KTOT - 1) { stage(p + 1, (p + 1) & 1); CP_COMMIT(); CP_WAIT1(); }
        else              { CP_WAIT0(); }
        __syncthreads();

        char* ubuf = smem + SM_U0 + (p & 1) * UB_PLANE;
        int rowA = w * 16 + lr + rsel;
#pragma unroll
        for (int kl = 0; kl < 4; kl++) {
            int colA = kl * 16 + csel;
            uint32_t a[4];
            ldm_x4(a, smem_u32(ubuf + rowA * 144 + colA * 2));
            int kk = p * 4 + kl;
#pragma unroll
            for (int oc = 0; oc < 8; oc++) {
                uint2 wh = wf[((0 * 20 + kk) * 8 + oc) * 32 + lane];
                uint2 wl = wf[((1 * 20 + kk) * 8 + oc) * 32 + lane];
                mma16816(acc[oc], a, wh.x, wh.y);
                mma16816(acc[oc], a, wl.x, wl.y);
            }
        }
        __syncthreads();
    }

    float* dout = reinterpret_cast<float*>(smem + SM_U0);   // [64][132]
    int g = lane >> 2, tg = lane & 3;
#pragma unroll
    for (int oc = 0; oc < 8; oc++) {
        int o = oc * 8 + 2 * tg;
        int ml = w * 16 + g;
        dout[o * 132 + ml]           = acc[oc][0];
        dout[(o + 1) * 132 + ml]     = acc[oc][1];
        dout[o * 132 + ml + 8]       = acc[oc][2];
        dout[(o + 1) * 132 + ml + 8] = acc[oc][3];
    }
    __syncthreads();

    int o = t >> 2, q = t & 3;
    float bv = __ldg(bias + o);
    float* yrow = y + ((size_t)b * 64 + o) * MM;
#pragma unroll
    for (int i = 0; i < 8; i++) {
        int c4 = q + i * 4;
        int m = mBase + c4 * 4;
        float4 v = *reinterpret_cast<float4*>(dout + o * 132 + c4 * 4);
        v.x += bv; v.y += bv; v.z += bv; v.w += bv;
        if (m + 3 < MM) {
            *reinterpret_cast<float4*>(yrow + m) = v;
        } else {
            if (m     < MM) yrow[m]     = v.x;
            if (m + 1 < MM) yrow[m + 1] = v.y;
            if (m + 2 < MM) yrow[m + 2] = v.z;
            if (m + 3 < MM) yrow[m + 3] = v.w;
        }
    }
}

// ---------------- launch ------------------------------------------------------
extern "C" void kernel_launch(void* const* d_in, const int* in_sizes, int n_in,
                              void* d_out, int out_size) {
    const int*   LlI  = (const int*)  d_in[0];
    const float* LlV  = (const float*)d_in[1];
    const int*   LuI  = (const int*)  d_in[2];
    const float* LuV  = (const float*)d_in[3];
    const float* x    = (const float*)d_in[4];
    const float* th   = (const float*)d_in[5];
    const float* bias = (const float*)d_in[6];
    float*       y    = (float*)d_out;
    int nnz = in_sizes[1];

    uint16_t* ubf;
    uint2* wfrag;
    cudaGetSymbolAddress((void**)&ubf,   g_ubf);
    cudaGetSymbolAddress((void**)&wfrag, g_wfrag);

    int  *cnt;
    int2 *ents;
    cudaGetSymbolAddress((void**)&cnt,  g_cnt);
    cudaGetSymbolAddress((void**)&ents, g_ents);

    cudaMemsetAsync(cnt, 0, 2 * MM * sizeof(int));

    int eb2 = (2 * nnz + 255) / 256;
    scatter_ell_kernel<<<eb2, 256>>>(LlI, LuI, LlV, LuV, cnt, ents, nnz);

    transpose_kernel<<<dim3(MM / 32, 4), dim3(32, 8)>>>(x);
    wprep_kernel<<<(2 * 20 * 8 * 32 + 255) / 256, 256>>>(th, wfrag);

    uint4* slot0 = reinterpret_cast<uint4*>(ubf);
    uint4* slot1 = reinterpret_cast<uint4*>(ubf + 1 * UBF_SLOT);
    uint4* slot2 = reinterpret_cast<uint4*>(ubf + 2 * UBF_SLOT);
    uint4* slot3 = reinterpret_cast<uint4*>(ubf + 3 * UBF_SLOT);
    uint4* slot4 = reinterpret_cast<uint4*>(ubf + 4 * UBF_SLOT);

    int spmmBlocks = (MM * 32 + 255) / 256;                 // 2 rows per warp
    spmm_dual_kernel<<<spmmBlocks, 256>>>(cnt, ents, slot0, slot0, slot1, slot3);
    spmm_dual_kernel<<<spmmBlocks, 256>>>(cnt, ents, slot1, slot3, slot2, slot4);

    cudaFuncSetAttribute(combine_kernel,
                         cudaFuncAttributeMaxDynamicSharedMemorySize, CMB_SMEM_BYTES);
    combine_kernel<<<dim3((MM + 127) / 128, 2), CMB_THREADS, CMB_SMEM_BYTES>>>(bias, y);
}

// round 15
// speedup vs baseline: 1.4652x; 1.0194x over previous
#include <cuda_runtime.h>
#include <cuda_fp16.h>
#include <cstdint>

#define MM    100000   // simplices
#define KTOT  5        // [x, Ll x, Ll^2 x, Lu x, Lu^2 x]
#define ELLW  32       // ELL row capacity (Poisson(8) tail @32 ~ 1e-11)
#define UBF_SLOT ((size_t)MM * 128)   // uint16 elems per k-slot (256B/row fp16)

// ---------------- scratch (device globals: no allocations allowed) ----------
__device__ __align__(16) uint16_t g_ubf[(size_t)KTOT * MM * 128];  // 128MB
__device__ __align__(16) uint2    g_wfrag[2 * 20 * 8 * 32];        // fp16 hi/lo W frags
__device__ int   g_cnt [2 * MM];
__device__ __align__(16) int2 g_ents[(size_t)2 * MM * ELLW];

// ---------------- helpers ----------------------------------------------------
__device__ __forceinline__ uint32_t smem_u32(const void* p) {
    uint32_t a;
    asm("{ .reg .u64 t; cvta.to.shared.u64 t, %1; cvt.u32.u64 %0, t; }"
        : "=r"(a) : "l"(p));
    return a;
}
__device__ __forceinline__ void cp_async8(uint32_t dst, const void* src, int szr) {
    asm volatile("cp.async.ca.shared.global [%0], [%1], 8, %2;"
                 :: "r"(dst), "l"(src), "r"(szr));
}
#define CP_COMMIT() asm volatile("cp.async.commit_group;" ::: "memory")
#define CP_WAIT1()  asm volatile("cp.async.wait_group 1;" ::: "memory")
#define CP_WAIT0()  asm volatile("cp.async.wait_group 0;" ::: "memory")

__device__ __forceinline__ void ldm_x4(uint32_t* r, uint32_t addr) {
    asm volatile("ldmatrix.sync.aligned.m8n8.x4.shared.b16 {%0,%1,%2,%3}, [%4];"
                 : "=r"(r[0]), "=r"(r[1]), "=r"(r[2]), "=r"(r[3]) : "r"(addr));
}
__device__ __forceinline__ void mma16816(float* c, const uint32_t* a,
                                         uint32_t b0, uint32_t b1) {
    asm volatile("mma.sync.aligned.m16n8k16.row.col.f32.f16.f16.f32 "
                 "{%0,%1,%2,%3}, {%4,%5,%6,%7}, {%8,%9}, {%0,%1,%2,%3};"
                 : "+f"(c[0]), "+f"(c[1]), "+f"(c[2]), "+f"(c[3])
                 : "r"(a[0]), "r"(a[1]), "r"(a[2]), "r"(a[3]), "r"(b0), "r"(b1));
}
__device__ __forceinline__ uint16_t h_bits(__half h) {
    return *reinterpret_cast<uint16_t*>(&h);
}
__device__ __forceinline__ float2 h2f(uint32_t u) {
    __half2 h = *reinterpret_cast<__half2*>(&u);
    return __half22float2(h);
}

// ---------------- 1) fused prep: wprep | transpose | scatter -----------------
#define NB_WPREP 40        // 10240 / 256
#define NB_TRANS 12500     // (MM/32) * 4

__global__ __launch_bounds__(256)
void prep_kernel(const float* __restrict__ x,
                 const int* __restrict__ LlI, const int* __restrict__ LuI,
                 const float* __restrict__ LlV, const float* __restrict__ LuV,
                 const float* __restrict__ theta,
                 int* __restrict__ cnt, int2* __restrict__ ents,
                 uint2* __restrict__ wfrag, int nnz) {
    __shared__ float tile[32][33];
    int t = threadIdx.x;
    int bid = blockIdx.x;

    if (bid < NB_WPREP) {
        // ---- wprep: theta -> fp16 hi/lo B fragments (mma register order) ----
        int i = bid * 256 + t;
        int lane = i & 31;
        int oc   = (i >> 5) & 7;
        int kk   = (i >> 8) % 20;
        int part = i / 5120;
        int tg = lane & 3, g = lane >> 2;
        int o = oc * 8 + g;
        const int kmap[KTOT] = {0, 1, 2, 4, 5};
        uint16_t bits[4];
#pragma unroll
        for (int e = 0; e < 4; e++) {
            int j = kk * 16 + 2 * tg + (e & 1) + (e >> 1) * 8;
            int kb = j >> 6, c = j & 63;
            float f = theta[(o * 64 + c) * 6 + kmap[kb]];
            if (kb == 0) f += theta[(o * 64 + c) * 6 + 3];
            __half h = __float2half_rn(f);
            if (part == 0) bits[e] = h_bits(h);
            else           bits[e] = h_bits(__float2half_rn(f - __half2float(h)));
        }
        wfrag[i] = make_uint2((uint32_t)bits[0] | ((uint32_t)bits[1] << 16),
                              (uint32_t)bits[2] | ((uint32_t)bits[3] << 16));
    } else if (bid < NB_WPREP + NB_TRANS) {
        // ---- transpose x (128, M) -> ubf slot 0 (fp16 linear) ----
        int b2 = bid - NB_WPREP;
        int mBase = (b2 % (MM / 32)) * 32;
        int fBase = (b2 / (MM / 32)) * 32;
        int tx = t & 31, ty = t >> 5;
#pragma unroll
        for (int i = 0; i < 32; i += 8)
            tile[ty + i][tx] = x[(size_t)(fBase + ty + i) * MM + mBase + tx];
        __syncthreads();
#pragma unroll
        for (int i = 0; i < 32; i += 8) {
            float v = tile[tx][ty + i];
            int m = mBase + ty + i, f = fBase + tx;
            g_ubf[(size_t)m * 128 + f] = h_bits(__float2half_rn(v));
        }
    } else {
        // ---- ELL scatter ----
        int e = (bid - NB_WPREP - NB_TRANS) * 256 + t;
        if (e >= 2 * nnz) return;
        int s = (e >= nnz);
        int el = e - s * nnz;
        int r   = s ? LuI[el]       : LlI[el];
        int c   = s ? LuI[el + nnz] : LlI[el + nnz];
        float v = s ? LuV[el]       : LlV[el];
        int idx = atomicAdd(&cnt[s * MM + r], 1);
        if (idx < ELLW)
            ents[(size_t)(s * MM + r) * ELLW + idx] = make_int2(c, __float_as_int(v));
    }
}

// ---------------- 2) dual ELL SpMM v4: 2 rows/warp, 2 x MLP-4 sub-batches ----
// Warp w handles row w of BOTH matrices: lanes 0-15 matrix 0, lanes 16-31
// matrix 1. Row = 16 uint4 (256B fp16). Gather state g[4] (halved registers).
__global__ __launch_bounds__(256)
void spmm_dual_kernel(const int* __restrict__ cnt, const int2* __restrict__ entsB,
                      const uint4* __restrict__ in0, const uint4* __restrict__ in1,
                      uint4* __restrict__ ob0, uint4* __restrict__ ob1) {
    int w = (blockIdx.x * blockDim.x + threadIdx.x) >> 5;   // row id
    if (w >= MM) return;
    int lane = threadIdx.x & 31;
    int hs = lane >> 4;          // matrix select for this half-warp
    int hl = lane & 15;          // uint4 index within 256B row
    const uint4* in = hs ? in1 : in0;

    int n = __ldg(cnt + hs * MM + w);
    n = n < ELLW ? n : ELLW;
    int noth = __shfl_xor_sync(0xffffffffu, n, 16);
    int nmax = n > noth ? n : noth;
    const int2* ents = entsB + (size_t)(hs * MM + w) * ELLW;

    float acc[8];
#pragma unroll
    for (int i = 0; i < 8; i++) acc[i] = 0.f;

    for (int base = 0; base < nmax; base += 8) {
        // one 8-entry lane-parallel fetch serves both sub-batches
        int2 my = __ldg(ents + base + (hl & 7));
#pragma unroll
        for (int half = 0; half < 2; half++) {
            int b4 = base + half * 4;
            int take = n - b4;
            take = take < 0 ? 0 : (take > 4 ? 4 : take);
            uint4 g[4];
            float v[4];
#pragma unroll
            for (int i = 0; i < 4; i++) {
                int src  = (lane & 16) + half * 4 + i;      // segmented shfl
                int col  = __shfl_sync(0xffffffffu, my.x, src);
                int vbit = __shfl_sync(0xffffffffu, my.y, src);
                bool ok = (i < take);
                v[i] = ok ? __int_as_float(vbit) : 0.f;
                col  = ok ? col : 0;
                g[i] = __ldg(in + (size_t)col * 16 + hl);   // MLP-4, 2 rows/warp
            }
#pragma unroll
            for (int i = 0; i < 4; i++) {
                float2 a0 = h2f(g[i].x), a1 = h2f(g[i].y);
                float2 a2 = h2f(g[i].z), a3 = h2f(g[i].w);
                acc[0] += v[i] * a0.x; acc[1] += v[i] * a0.y;
                acc[2] += v[i] * a1.x; acc[3] += v[i] * a1.y;
                acc[4] += v[i] * a2.x; acc[5] += v[i] * a2.y;
                acc[6] += v[i] * a3.x; acc[7] += v[i] * a3.y;
            }
        }
    }

    __half2 o0 = __floats2half2_rn(acc[0], acc[1]);
    __half2 o1 = __floats2half2_rn(acc[2], acc[3]);
    __half2 o2 = __floats2half2_rn(acc[4], acc[5]);
    __half2 o3 = __floats2half2_rn(acc[6], acc[7]);
    uint4 o;
    o.x = *reinterpret_cast<uint32_t*>(&o0);
    o.y = *reinterpret_cast<uint32_t*>(&o1);
    o.z = *reinterpret_cast<uint32_t*>(&o2);
    o.w = *reinterpret_cast<uint32_t*>(&o3);
    (hs ? ob1 : ob0)[(size_t)w * 16 + hl] = o;
}

// ---------------- 4) combine: warp-level fp16 MMA (u*wh + u*wl) -------------
#define CMB_THREADS 256
#define SM_WF    0
#define WF_BYTES 81920
#define UB_PLANE 18432                  // 128 rows * 144B (64ch fp16 + pad)
#define SM_U0    WF_BYTES
#define CMB_SMEM_BYTES (WF_BYTES + 2 * UB_PLANE)   // 118784

__global__ __launch_bounds__(CMB_THREADS, 1)
void combine_kernel(const float* __restrict__ bias, float* __restrict__ y) {
    extern __shared__ char smem[];
    int t = threadIdx.x;
    int lane = t & 31, w = t >> 5;
    int b = blockIdx.y;
    int mBase = blockIdx.x * 128;

    {
        const float4* src = reinterpret_cast<const float4*>(g_wfrag);
        float4* dst = reinterpret_cast<float4*>(smem + SM_WF);
#pragma unroll
        for (int i = t; i < WF_BYTES / 16; i += CMB_THREADS)
            dst[i] = src[i];
    }

    float acc[8][4];
#pragma unroll
    for (int oc = 0; oc < 8; oc++)
#pragma unroll
        for (int e = 0; e < 4; e++) acc[oc][e] = 0.f;

    auto stage = [&](int p, int buf) {
        const char* srcb = reinterpret_cast<const char*>(g_ubf + (size_t)p * UBF_SLOT);
        char* dbase = smem + SM_U0 + buf * UB_PLANE;
#pragma unroll
        for (int jj = 0; jj < 8; jj++) {
            int idx = t + jj * CMB_THREADS;      // 0..2047
            int row = idx >> 4;
            int i   = idx & 15;
            int mm = mBase + row;
            int ok = (mm < MM);
            const char* sp = srcb + (size_t)(ok ? mm : 0) * 256 + b * 128 + i * 8;
            uint32_t d = smem_u32(dbase + row * 144 + i * 8);
            cp_async8(d, sp, ok ? 8 : 0);
        }
    };

    stage(0, 0);
    CP_COMMIT();

    const uint2* wf = reinterpret_cast<const uint2*>(smem + SM_WF);
    int lr = lane & 7;
    int rsel = (lane & 8) ? 8 : 0;
    int csel = (lane & 16) ? 8 : 0;

#pragma unroll 1
    for (int p = 0; p < KTOT; p++) {
        if (p < KTOT - 1) { stage(p + 1, (p + 1) & 1); CP_COMMIT(); CP_WAIT1(); }
        else              { CP_WAIT0(); }
        __syncthreads();

        char* ubuf = smem + SM_U0 + (p & 1) * UB_PLANE;
        int rowA = w * 16 + lr + rsel;
#pragma unroll
        for (int kl = 0; kl < 4; kl++) {
            int colA = kl * 16 + csel;
            uint32_t a[4];
            ldm_x4(a, smem_u32(ubuf + rowA * 144 + colA * 2));
            int kk = p * 4 + kl;
#pragma unroll
            for (int oc = 0; oc < 8; oc++) {
                uint2 wh = wf[((0 * 20 + kk) * 8 + oc) * 32 + lane];
                uint2 wl = wf[((1 * 20 + kk) * 8 + oc) * 32 + lane];
                mma16816(acc[oc], a, wh.x, wh.y);
                mma16816(acc[oc], a, wl.x, wl.y);
            }
        }
        __syncthreads();
    }

    float* dout = reinterpret_cast<float*>(smem + SM_U0);   // [64][132]
    int g = lane >> 2, tg = lane & 3;
#pragma unroll
    for (int oc = 0; oc < 8; oc++) {
        int o = oc * 8 + 2 * tg;
        int ml = w * 16 + g;
        dout[o * 132 + ml]           = acc[oc][0];
        dout[(o + 1) * 132 + ml]     = acc[oc][1];
        dout[o * 132 + ml + 8]       = acc[oc][2];
        dout[(o + 1) * 132 + ml + 8] = acc[oc][3];
    }
    __syncthreads();

    int o = t >> 2, q = t & 3;
    float bv = __ldg(bias + o);
    float* yrow = y + ((size_t)b * 64 + o) * MM;
#pragma unroll
    for (int i = 0; i < 8; i++) {
        int c4 = q + i * 4;
        int m = mBase + c4 * 4;
        float4 v = *reinterpret_cast<float4*>(dout + o * 132 + c4 * 4);
        v.x += bv; v.y += bv; v.z += bv; v.w += bv;
        if (m + 3 < MM) {
            *reinterpret_cast<float4*>(yrow + m) = v;
        } else {
            if (m     < MM) yrow[m]     = v.x;
            if (m + 1 < MM) yrow[m + 1] = v.y;
            if (m + 2 < MM) yrow[m + 2] = v.z;
            if (m + 3 < MM) yrow[m + 3] = v.w;
        }
    }
}

// ---------------- launch ------------------------------------------------------
extern "C" void kernel_launch(void* const* d_in, const int* in_sizes, int n_in,
                              void* d_out, int out_size) {
    const int*   LlI  = (const int*)  d_in[0];
    const float* LlV  = (const float*)d_in[1];
    const int*   LuI  = (const int*)  d_in[2];
    const float* LuV  = (const float*)d_in[3];
    const float* x    = (const float*)d_in[4];
    const float* th   = (const float*)d_in[5];
    const float* bias = (const float*)d_in[6];
    float*       y    = (float*)d_out;
    int nnz = in_sizes[1];

    uint16_t* ubf;
    uint2* wfrag;
    cudaGetSymbolAddress((void**)&ubf,   g_ubf);
    cudaGetSymbolAddress((void**)&wfrag, g_wfrag);

    int  *cnt;
    int2 *ents;
    cudaGetSymbolAddress((void**)&cnt,  g_cnt);
    cudaGetSymbolAddress((void**)&ents, g_ents);

    cudaMemsetAsync(cnt, 0, 2 * MM * sizeof(int));

    int eb2 = (2 * nnz + 255) / 256;
    prep_kernel<<<NB_WPREP + NB_TRANS + eb2, 256>>>(
        x, LlI, LuI, LlV, LuV, th, cnt, ents, wfrag, nnz);

    uint4* slot0 = reinterpret_cast<uint4*>(ubf);
    uint4* slot1 = reinterpret_cast<uint4*>(ubf + 1 * UBF_SLOT);
    uint4* slot2 = reinterpret_cast<uint4*>(ubf + 2 * UBF_SLOT);
    uint4* slot3 = reinterpret_cast<uint4*>(ubf + 3 * UBF_SLOT);
    uint4* slot4 = reinterpret_cast<uint4*>(ubf + 4 * UBF_SLOT);

    int spmmBlocks = (MM * 32 + 255) / 256;                 // 2 rows per warp
    spmm_dual_kernel<<<spmmBlocks, 256>>>(cnt, ents, slot0, slot0, slot1, slot3);
    spmm_dual_kernel<<<spmmBlocks, 256>>>(cnt, ents, slot1, slot3, slot2, slot4);

    cudaFuncSetAttribute(combine_kernel,
                         cudaFuncAttributeMaxDynamicSharedMemorySize, CMB_SMEM_BYTES);
    combine_kernel<<<dim3((MM + 127) / 128, 2), CMB_THREADS, CMB_SMEM_BYTES>>>(bias, y);
}

// round 16
// speedup vs baseline: 1.5687x; 1.0707x over previous
#include <cuda_runtime.h>
#include <cuda_fp16.h>
#include <cstdint>

#define MM    100000   // simplices
#define KTOT  5        // [x, Ll x, Ll^2 x, Lu x, Lu^2 x]
#define ELLW  32       // ELL row capacity (Poisson(8) tail @32 ~ 1e-11)
#define UBF_SLOT ((size_t)MM * 128)   // uint16 elems per k-slot (256B/row fp16)

// ---------------- scratch (device globals: no allocations allowed) ----------
__device__ __align__(16) uint16_t g_ubf[(size_t)KTOT * MM * 128];  // 128MB
// W fragments: [kk(20)][oc(8)][lane(32)] x uint4 {wh.x,wh.y,wl.x,wl.y} = 80KB
__device__ __align__(16) uint4   g_wfrag[20 * 8 * 32];
__device__ int   g_cnt [2 * MM];
__device__ __align__(16) int2 g_ents[(size_t)2 * MM * ELLW];

// ---------------- helpers ----------------------------------------------------
__device__ __forceinline__ uint32_t smem_u32(const void* p) {
    uint32_t a;
    asm("{ .reg .u64 t; cvta.to.shared.u64 t, %1; cvt.u32.u64 %0, t; }"
        : "=r"(a) : "l"(p));
    return a;
}
__device__ __forceinline__ void cp_async8(uint32_t dst, const void* src, int szr) {
    asm volatile("cp.async.ca.shared.global [%0], [%1], 8, %2;"
                 :: "r"(dst), "l"(src), "r"(szr));
}
__device__ __forceinline__ void cp_async16(uint32_t dst, const void* src) {
    asm volatile("cp.async.cg.shared.global [%0], [%1], 16;"
                 :: "r"(dst), "l"(src));
}
#define CP_COMMIT() asm volatile("cp.async.commit_group;" ::: "memory")
#define CP_WAIT1()  asm volatile("cp.async.wait_group 1;" ::: "memory")
#define CP_WAIT0()  asm volatile("cp.async.wait_group 0;" ::: "memory")

__device__ __forceinline__ void ldm_x4(uint32_t* r, uint32_t addr) {
    asm volatile("ldmatrix.sync.aligned.m8n8.x4.shared.b16 {%0,%1,%2,%3}, [%4];"
                 : "=r"(r[0]), "=r"(r[1]), "=r"(r[2]), "=r"(r[3]) : "r"(addr));
}
__device__ __forceinline__ void mma16816(float* c, const uint32_t* a,
                                         uint32_t b0, uint32_t b1) {
    asm volatile("mma.sync.aligned.m16n8k16.row.col.f32.f16.f16.f32 "
                 "{%0,%1,%2,%3}, {%4,%5,%6,%7}, {%8,%9}, {%0,%1,%2,%3};"
                 : "+f"(c[0]), "+f"(c[1]), "+f"(c[2]), "+f"(c[3])
                 : "r"(a[0]), "r"(a[1]), "r"(a[2]), "r"(a[3]), "r"(b0), "r"(b1));
}
__device__ __forceinline__ uint16_t h_bits(__half h) {
    return *reinterpret_cast<uint16_t*>(&h);
}
__device__ __forceinline__ float2 h2f(uint32_t u) {
    __half2 h = *reinterpret_cast<__half2*>(&u);
    return __half22float2(h);
}

// ---------------- 1) fused prep: wprep | transpose | scatter -----------------
#define NB_WPREP 40        // 10240 / 256
#define NB_TRANS 12500     // (MM/32) * 4

__global__ __launch_bounds__(256)
void prep_kernel(const float* __restrict__ x,
                 const int* __restrict__ LlI, const int* __restrict__ LuI,
                 const float* __restrict__ LlV, const float* __restrict__ LuV,
                 const float* __restrict__ theta,
                 int* __restrict__ cnt, int2* __restrict__ ents,
                 uint2* __restrict__ wfrag, int nnz) {
    __shared__ float tile[32][33];
    int t = threadIdx.x;
    int bid = blockIdx.x;

    if (bid < NB_WPREP) {
        // ---- wprep: theta -> fp16 hi/lo B fragments, wh/wl interleaved ------
        int i = bid * 256 + t;
        int lane = i & 31;
        int oc   = (i >> 5) & 7;
        int kk   = (i >> 8) % 20;
        int part = i / 5120;
        int tg = lane & 3, g = lane >> 2;
        int o = oc * 8 + g;
        const int kmap[KTOT] = {0, 1, 2, 4, 5};
        uint16_t bits[4];
#pragma unroll
        for (int e = 0; e < 4; e++) {
            int j = kk * 16 + 2 * tg + (e & 1) + (e >> 1) * 8;
            int kb = j >> 6, c = j & 63;
            float f = theta[(o * 64 + c) * 6 + kmap[kb]];
            if (kb == 0) f += theta[(o * 64 + c) * 6 + 3];
            __half h = __float2half_rn(f);
            if (part == 0) bits[e] = h_bits(h);
            else           bits[e] = h_bits(__float2half_rn(f - __half2float(h)));
        }
        // uint4 slot = ((kk*8+oc)*32+lane); part selects low/high uint2
        wfrag[((kk * 8 + oc) * 32 + lane) * 2 + part] =
            make_uint2((uint32_t)bits[0] | ((uint32_t)bits[1] << 16),
                       (uint32_t)bits[2] | ((uint32_t)bits[3] << 16));
    } else if (bid < NB_WPREP + NB_TRANS) {
        // ---- transpose x (128, M) -> ubf slot 0 (fp16 linear) ----
        int b2 = bid - NB_WPREP;
        int mBase = (b2 % (MM / 32)) * 32;
        int fBase = (b2 / (MM / 32)) * 32;
        int tx = t & 31, ty = t >> 5;
#pragma unroll
        for (int i = 0; i < 32; i += 8)
            tile[ty + i][tx] = x[(size_t)(fBase + ty + i) * MM + mBase + tx];
        __syncthreads();
#pragma unroll
        for (int i = 0; i < 32; i += 8) {
            float v = tile[tx][ty + i];
            int m = mBase + ty + i, f = fBase + tx;
            g_ubf[(size_t)m * 128 + f] = h_bits(__float2half_rn(v));
        }
    } else {
        // ---- ELL scatter ----
        int e = (bid - NB_WPREP - NB_TRANS) * 256 + t;
        if (e >= 2 * nnz) return;
        int s = (e >= nnz);
        int el = e - s * nnz;
        int r   = s ? LuI[el]       : LlI[el];
        int c   = s ? LuI[el + nnz] : LlI[el + nnz];
        float v = s ? LuV[el]       : LlV[el];
        int idx = atomicAdd(&cnt[s * MM + r], 1);
        if (idx < ELLW)
            ents[(size_t)(s * MM + r) * ELLW + idx] = make_int2(c, __float_as_int(v));
    }
}

// ---------------- 2) dual ELL SpMM: 2 rows/warp, 2 x MLP-4 sub-batches -------
__global__ __launch_bounds__(256)
void spmm_dual_kernel(const int* __restrict__ cnt, const int2* __restrict__ entsB,
                      const uint4* __restrict__ in0, const uint4* __restrict__ in1,
                      uint4* __restrict__ ob0, uint4* __restrict__ ob1) {
    int w = (blockIdx.x * blockDim.x + threadIdx.x) >> 5;   // row id
    if (w >= MM) return;
    int lane = threadIdx.x & 31;
    int hs = lane >> 4;          // matrix select for this half-warp
    int hl = lane & 15;          // uint4 index within 256B row
    const uint4* in = hs ? in1 : in0;

    int n = __ldg(cnt + hs * MM + w);
    n = n < ELLW ? n : ELLW;
    int noth = __shfl_xor_sync(0xffffffffu, n, 16);
    int nmax = n > noth ? n : noth;
    const int2* ents = entsB + (size_t)(hs * MM + w) * ELLW;

    float acc[8];
#pragma unroll
    for (int i = 0; i < 8; i++) acc[i] = 0.f;

    for (int base = 0; base < nmax; base += 8) {
        int2 my = __ldg(ents + base + (hl & 7));
#pragma unroll
        for (int half = 0; half < 2; half++) {
            int b4 = base + half * 4;
            int take = n - b4;
            take = take < 0 ? 0 : (take > 4 ? 4 : take);
            uint4 g[4];
            float v[4];
#pragma unroll
            for (int i = 0; i < 4; i++) {
                int src  = (lane & 16) + half * 4 + i;      // segmented shfl
                int col  = __shfl_sync(0xffffffffu, my.x, src);
                int vbit = __shfl_sync(0xffffffffu, my.y, src);
                bool ok = (i < take);
                v[i] = ok ? __int_as_float(vbit) : 0.f;
                col  = ok ? col : 0;
                g[i] = __ldg(in + (size_t)col * 16 + hl);   // MLP-4, 2 rows/warp
            }
#pragma unroll
            for (int i = 0; i < 4; i++) {
                float2 a0 = h2f(g[i].x), a1 = h2f(g[i].y);
                float2 a2 = h2f(g[i].z), a3 = h2f(g[i].w);
                acc[0] += v[i] * a0.x; acc[1] += v[i] * a0.y;
                acc[2] += v[i] * a1.x; acc[3] += v[i] * a1.y;
                acc[4] += v[i] * a2.x; acc[5] += v[i] * a2.y;
                acc[6] += v[i] * a3.x; acc[7] += v[i] * a3.y;
            }
        }
    }

    __half2 o0 = __floats2half2_rn(acc[0], acc[1]);
    __half2 o1 = __floats2half2_rn(acc[2], acc[3]);
    __half2 o2 = __floats2half2_rn(acc[4], acc[5]);
    __half2 o3 = __floats2half2_rn(acc[6], acc[7]);
    uint4 o;
    o.x = *reinterpret_cast<uint32_t*>(&o0);
    o.y = *reinterpret_cast<uint32_t*>(&o1);
    o.z = *reinterpret_cast<uint32_t*>(&o2);
    o.w = *reinterpret_cast<uint32_t*>(&o3);
    (hs ? ob1 : ob0)[(size_t)w * 16 + hl] = o;
}

// ---------------- 4) combine v7: per-phase W staging, 2 CTAs/SM -------------
// smem: 2 x Wslice(16KB) + 2 x Uplane(18KB) = 69.6KB; launch_bounds(256,2)
// forces regs<=128 -> 2 CTAs/SM (16 warps). wh/wl in one LDS.128.
#define CMB_THREADS 256
#define W_SLICE  16384                  // 4 kl x 8 oc x 32 lanes x 16B
#define SM_U0    (2 * W_SLICE)          // 32768
#define UB_PLANE 18432                  // 128 rows * 144B (64ch fp16 + pad)
#define CMB_SMEM_BYTES (SM_U0 + 2 * UB_PLANE)   // 69632

__global__ __launch_bounds__(CMB_THREADS, 2)
void combine_kernel(const float* __restrict__ bias, float* __restrict__ y) {
    extern __shared__ char smem[];
    int t = threadIdx.x;
    int lane = t & 31, w = t >> 5;
    int b = blockIdx.y;
    int mBase = blockIdx.x * 128;

    float acc[8][4];
#pragma unroll
    for (int oc = 0; oc < 8; oc++)
#pragma unroll
        for (int e = 0; e < 4; e++) acc[oc][e] = 0.f;

    // stage phase p (W 16KB slice + U 32KB tile) into buffer p&1
    auto stage = [&](int p, int buf) {
        const char* wsrc = reinterpret_cast<const char*>(g_wfrag) + (size_t)p * W_SLICE;
        char* wdst = smem + buf * W_SLICE;
#pragma unroll
        for (int jj = 0; jj < 4; jj++) {
            int idx = t + jj * CMB_THREADS;      // 0..1023 x 16B
            cp_async16(smem_u32(wdst + idx * 16), wsrc + idx * 16);
        }
        const char* srcb = reinterpret_cast<const char*>(g_ubf + (size_t)p * UBF_SLOT);
        char* dbase = smem + SM_U0 + buf * UB_PLANE;
#pragma unroll
        for (int jj = 0; jj < 8; jj++) {
            int idx = t + jj * CMB_THREADS;      // 0..2047
            int row = idx >> 4;
            int i   = idx & 15;
            int mm = mBase + row;
            int ok = (mm < MM);
            const char* sp = srcb + (size_t)(ok ? mm : 0) * 256 + b * 128 + i * 8;
            uint32_t d = smem_u32(dbase + row * 144 + i * 8);
            cp_async8(d, sp, ok ? 8 : 0);
        }
    };

    stage(0, 0);
    CP_COMMIT();

    int lr = lane & 7;
    int rsel = (lane & 8) ? 8 : 0;
    int csel = (lane & 16) ? 8 : 0;

#pragma unroll 1
    for (int p = 0; p < KTOT; p++) {
        if (p < KTOT - 1) { stage(p + 1, (p + 1) & 1); CP_COMMIT(); CP_WAIT1(); }
        else              { CP_WAIT0(); }
        __syncthreads();

        const uint4* wb = reinterpret_cast<const uint4*>(smem + (p & 1) * W_SLICE);
        char* ubuf = smem + SM_U0 + (p & 1) * UB_PLANE;
        int rowA = w * 16 + lr + rsel;
#pragma unroll
        for (int kl = 0; kl < 4; kl++) {
            int colA = kl * 16 + csel;
            uint32_t a[4];
            ldm_x4(a, smem_u32(ubuf + rowA * 144 + colA * 2));
#pragma unroll
            for (int oc = 0; oc < 8; oc++) {
                uint4 wv = wb[(kl * 8 + oc) * 32 + lane];   // one LDS.128: wh|wl
                mma16816(acc[oc], a, wv.x, wv.y);
                mma16816(acc[oc], a, wv.z, wv.w);
            }
        }
        __syncthreads();
    }

    // epilogue: transpose D through smem (reuse U buffers, 36.8KB >= 33.8KB)
    float* dout = reinterpret_cast<float*>(smem + SM_U0);   // [64][132]
    int g = lane >> 2, tg = lane & 3;
#pragma unroll
    for (int oc = 0; oc < 8; oc++) {
        int o = oc * 8 + 2 * tg;
        int ml = w * 16 + g;
        dout[o * 132 + ml]           = acc[oc][0];
        dout[(o + 1) * 132 + ml]     = acc[oc][1];
        dout[o * 132 + ml + 8]       = acc[oc][2];
        dout[(o + 1) * 132 + ml + 8] = acc[oc][3];
    }
    __syncthreads();

    int o = t >> 2, q = t & 3;
    float bv = __ldg(bias + o);
    float* yrow = y + ((size_t)b * 64 + o) * MM;
#pragma unroll
    for (int i = 0; i < 8; i++) {
        int c4 = q + i * 4;
        int m = mBase + c4 * 4;
        float4 v = *reinterpret_cast<float4*>(dout + o * 132 + c4 * 4);
        v.x += bv; v.y += bv; v.z += bv; v.w += bv;
        if (m + 3 < MM) {
            *reinterpret_cast<float4*>(yrow + m) = v;
        } else {
            if (m     < MM) yrow[m]     = v.x;
            if (m + 1 < MM) yrow[m + 1] = v.y;
            if (m + 2 < MM) yrow[m + 2] = v.z;
            if (m + 3 < MM) yrow[m + 3] = v.w;
        }
    }
}

// ---------------- launch ------------------------------------------------------
extern "C" void kernel_launch(void* const* d_in, const int* in_sizes, int n_in,
                              void* d_out, int out_size) {
    const int*   LlI  = (const int*)  d_in[0];
    const float* LlV  = (const float*)d_in[1];
    const int*   LuI  = (const int*)  d_in[2];
    const float* LuV  = (const float*)d_in[3];
    const float* x    = (const float*)d_in[4];
    const float* th   = (const float*)d_in[5];
    const float* bias = (const float*)d_in[6];
    float*       y    = (float*)d_out;
    int nnz = in_sizes[1];

    uint16_t* ubf;
    uint4* wfrag;
    cudaGetSymbolAddress((void**)&ubf,   g_ubf);
    cudaGetSymbolAddress((void**)&wfrag, g_wfrag);

    int  *cnt;
    int2 *ents;
    cudaGetSymbolAddress((void**)&cnt,  g_cnt);
    cudaGetSymbolAddress((void**)&ents, g_ents);

    cudaMemsetAsync(cnt, 0, 2 * MM * sizeof(int));

    int eb2 = (2 * nnz + 255) / 256;
    prep_kernel<<<NB_WPREP + NB_TRANS + eb2, 256>>>(
        x, LlI, LuI, LlV, LuV, th, cnt, ents,
        reinterpret_cast<uint2*>(wfrag), nnz);

    uint4* slot0 = reinterpret_cast<uint4*>(ubf);
    uint4* slot1 = reinterpret_cast<uint4*>(ubf + 1 * UBF_SLOT);
    uint4* slot2 = reinterpret_cast<uint4*>(ubf + 2 * UBF_SLOT);
    uint4* slot3 = reinterpret_cast<uint4*>(ubf + 3 * UBF_SLOT);
    uint4* slot4 = reinterpret_cast<uint4*>(ubf + 4 * UBF_SLOT);

    int spmmBlocks = (MM * 32 + 255) / 256;                 // 2 rows per warp
    spmm_dual_kernel<<<spmmBlocks, 256>>>(cnt, ents, slot0, slot0, slot1, slot3);
    spmm_dual_kernel<<<spmmBlocks, 256>>>(cnt, ents, slot1, slot3, slot2, slot4);

    cudaFuncSetAttribute(combine_kernel,
                         cudaFuncAttributeMaxDynamicSharedMemorySize, CMB_SMEM_BYTES);
    combine_kernel<<<dim3((MM + 127) / 128, 2), CMB_THREADS, CMB_SMEM_BYTES>>>(bias, y);
}

// round 17
// speedup vs baseline: 1.6367x; 1.0433x over previous
#include <cuda_runtime.h>
#include <cuda_fp16.h>
#include <cstdint>

#define MM    100000   // simplices
#define KTOT  5        // [x, Ll x, Ll^2 x, Lu x, Lu^2 x]
#define ELLW  32       // ELL row capacity (Poisson(8) tail @32 ~ 1e-11)
#define UBF_SLOT ((size_t)MM * 128)   // uint16 elems per k-slot (256B/row fp16)

// ---------------- scratch (device globals: no allocations allowed) ----------
__device__ __align__(16) uint16_t g_ubf[(size_t)KTOT * MM * 128];  // 128MB
// W fragments: [kk(20)][oc(8)][lane(32)] x uint4 {wh.x,wh.y,wl.x,wl.y} = 80KB
__device__ __align__(16) uint4   g_wfrag[20 * 8 * 32];
__device__ int   g_cnt [2 * MM];
__device__ __align__(16) int2 g_ents[(size_t)2 * MM * ELLW];

// ---------------- helpers ----------------------------------------------------
__device__ __forceinline__ uint32_t smem_u32(const void* p) {
    uint32_t a;
    asm("{ .reg .u64 t; cvta.to.shared.u64 t, %1; cvt.u32.u64 %0, t; }"
        : "=r"(a) : "l"(p));
    return a;
}
__device__ __forceinline__ void cp_async8(uint32_t dst, const void* src, int szr) {
    asm volatile("cp.async.ca.shared.global [%0], [%1], 8, %2;"
                 :: "r"(dst), "l"(src), "r"(szr));
}
__device__ __forceinline__ void cp_async16(uint32_t dst, const void* src) {
    asm volatile("cp.async.cg.shared.global [%0], [%1], 16;"
                 :: "r"(dst), "l"(src));
}
#define CP_COMMIT() asm volatile("cp.async.commit_group;" ::: "memory")
#define CP_WAIT1()  asm volatile("cp.async.wait_group 1;" ::: "memory")
#define CP_WAIT0()  asm volatile("cp.async.wait_group 0;" ::: "memory")

__device__ __forceinline__ void ldm_x4(uint32_t* r, uint32_t addr) {
    asm volatile("ldmatrix.sync.aligned.m8n8.x4.shared.b16 {%0,%1,%2,%3}, [%4];"
                 : "=r"(r[0]), "=r"(r[1]), "=r"(r[2]), "=r"(r[3]) : "r"(addr));
}
__device__ __forceinline__ void mma16816(float* c, const uint32_t* a,
                                         uint32_t b0, uint32_t b1) {
    asm volatile("mma.sync.aligned.m16n8k16.row.col.f32.f16.f16.f32 "
                 "{%0,%1,%2,%3}, {%4,%5,%6,%7}, {%8,%9}, {%0,%1,%2,%3};"
                 : "+f"(c[0]), "+f"(c[1]), "+f"(c[2]), "+f"(c[3])
                 : "r"(a[0]), "r"(a[1]), "r"(a[2]), "r"(a[3]), "r"(b0), "r"(b1));
}
__device__ __forceinline__ uint16_t h_bits(__half h) {
    return *reinterpret_cast<uint16_t*>(&h);
}
__device__ __forceinline__ float2 h2f(uint32_t u) {
    __half2 h = *reinterpret_cast<__half2*>(&u);
    return __half22float2(h);
}

// ---------------- 1) fused prep: wprep | transpose | scatter -----------------
#define NB_WPREP 40        // 10240 / 256
#define NB_TRANS 12500     // (MM/32) * 4

__global__ __launch_bounds__(256)
void prep_kernel(const float* __restrict__ x,
                 const int* __restrict__ LlI, const int* __restrict__ LuI,
                 const float* __restrict__ LlV, const float* __restrict__ LuV,
                 const float* __restrict__ theta,
                 int* __restrict__ cnt, int2* __restrict__ ents,
                 uint2* __restrict__ wfrag, int nnz) {
    __shared__ float tile[32][33];
    int t = threadIdx.x;
    int bid = blockIdx.x;

    if (bid < NB_WPREP) {
        // ---- wprep: theta -> fp16 hi/lo B fragments, wh/wl interleaved ------
        int i = bid * 256 + t;
        int lane = i & 31;
        int oc   = (i >> 5) & 7;
        int kk   = (i >> 8) % 20;
        int part = i / 5120;
        int tg = lane & 3, g = lane >> 2;
        int o = oc * 8 + g;
        const int kmap[KTOT] = {0, 1, 2, 4, 5};
        uint16_t bits[4];
#pragma unroll
        for (int e = 0; e < 4; e++) {
            int j = kk * 16 + 2 * tg + (e & 1) + (e >> 1) * 8;
            int kb = j >> 6, c = j & 63;
            float f = theta[(o * 64 + c) * 6 + kmap[kb]];
            if (kb == 0) f += theta[(o * 64 + c) * 6 + 3];
            __half h = __float2half_rn(f);
            if (part == 0) bits[e] = h_bits(h);
            else           bits[e] = h_bits(__float2half_rn(f - __half2float(h)));
        }
        wfrag[((kk * 8 + oc) * 32 + lane) * 2 + part] =
            make_uint2((uint32_t)bits[0] | ((uint32_t)bits[1] << 16),
                       (uint32_t)bits[2] | ((uint32_t)bits[3] << 16));
    } else if (bid < NB_WPREP + NB_TRANS) {
        // ---- transpose x (128, M) -> ubf slot 0 (fp16 linear) ----
        int b2 = bid - NB_WPREP;
        int mBase = (b2 % (MM / 32)) * 32;
        int fBase = (b2 / (MM / 32)) * 32;
        int tx = t & 31, ty = t >> 5;
#pragma unroll
        for (int i = 0; i < 32; i += 8)
            tile[ty + i][tx] = x[(size_t)(fBase + ty + i) * MM + mBase + tx];
        __syncthreads();
#pragma unroll
        for (int i = 0; i < 32; i += 8) {
            float v = tile[tx][ty + i];
            int m = mBase + ty + i, f = fBase + tx;
            g_ubf[(size_t)m * 128 + f] = h_bits(__float2half_rn(v));
        }
    } else {
        // ---- ELL scatter ----
        int e = (bid - NB_WPREP - NB_TRANS) * 256 + t;
        if (e >= 2 * nnz) return;
        int s = (e >= nnz);
        int el = e - s * nnz;
        int r   = s ? LuI[el]       : LlI[el];
        int c   = s ? LuI[el + nnz] : LlI[el + nnz];
        float v = s ? LuV[el]       : LlV[el];
        int idx = atomicAdd(&cnt[s * MM + r], 1);
        if (idx < ELLW)
            ents[(size_t)(s * MM + r) * ELLW + idx] = make_int2(c, __float_as_int(v));
    }
}

// ---------------- 2) dual ELL SpMM: 2 rows/warp, 2 x MLP-4 sub-batches -------
__global__ __launch_bounds__(256)
void spmm_dual_kernel(const int* __restrict__ cnt, const int2* __restrict__ entsB,
                      const uint4* __restrict__ in0, const uint4* __restrict__ in1,
                      uint4* __restrict__ ob0, uint4* __restrict__ ob1) {
    int w = (blockIdx.x * blockDim.x + threadIdx.x) >> 5;   // row id
    if (w >= MM) return;
    int lane = threadIdx.x & 31;
    int hs = lane >> 4;          // matrix select for this half-warp
    int hl = lane & 15;          // uint4 index within 256B row
    const uint4* in = hs ? in1 : in0;

    int n = __ldg(cnt + hs * MM + w);
    n = n < ELLW ? n : ELLW;
    int noth = __shfl_xor_sync(0xffffffffu, n, 16);
    int nmax = n > noth ? n : noth;
    const int2* ents = entsB + (size_t)(hs * MM + w) * ELLW;

    float acc[8];
#pragma unroll
    for (int i = 0; i < 8; i++) acc[i] = 0.f;

    for (int base = 0; base < nmax; base += 8) {
        int2 my = __ldg(ents + base + (hl & 7));
#pragma unroll
        for (int half = 0; half < 2; half++) {
            int b4 = base + half * 4;
            int take = n - b4;
            take = take < 0 ? 0 : (take > 4 ? 4 : take);
            uint4 g[4];
            float v[4];
#pragma unroll
            for (int i = 0; i < 4; i++) {
                int src  = (lane & 16) + half * 4 + i;      // segmented shfl
                int col  = __shfl_sync(0xffffffffu, my.x, src);
                int vbit = __shfl_sync(0xffffffffu, my.y, src);
                bool ok = (i < take);
                v[i] = ok ? __int_as_float(vbit) : 0.f;
                col  = ok ? col : 0;
                g[i] = __ldg(in + (size_t)col * 16 + hl);   // MLP-4, 2 rows/warp
            }
#pragma unroll
            for (int i = 0; i < 4; i++) {
                float2 a0 = h2f(g[i].x), a1 = h2f(g[i].y);
                float2 a2 = h2f(g[i].z), a3 = h2f(g[i].w);
                acc[0] += v[i] * a0.x; acc[1] += v[i] * a0.y;
                acc[2] += v[i] * a1.x; acc[3] += v[i] * a1.y;
                acc[4] += v[i] * a2.x; acc[5] += v[i] * a2.y;
                acc[6] += v[i] * a3.x; acc[7] += v[i] * a3.y;
            }
        }
    }

    __half2 o0 = __floats2half2_rn(acc[0], acc[1]);
    __half2 o1 = __floats2half2_rn(acc[2], acc[3]);
    __half2 o2 = __floats2half2_rn(acc[4], acc[5]);
    __half2 o3 = __floats2half2_rn(acc[6], acc[7]);
    uint4 o;
    o.x = *reinterpret_cast<uint32_t*>(&o0);
    o.y = *reinterpret_cast<uint32_t*>(&o1);
    o.z = *reinterpret_cast<uint32_t*>(&o2);
    o.w = *reinterpret_cast<uint32_t*>(&o3);
    (hs ? ob1 : ob0)[(size_t)w * 16 + hl] = o;
}

// ---------------- 4) combine v8: warp owns 32m x 32o (half the W LDS) -------
// 8 warps: ms = w&3 (m-strip of 32 rows), oh = w>>2 (o-half of 32).
// Per warp per phase: 8 ldmatrix (A) + 16 LDS.128 (W) vs 4 + 32 before.
#define CMB_THREADS 256
#define W_SLICE  16384                  // 4 kl x 8 oc x 32 lanes x 16B
#define SM_U0    (2 * W_SLICE)          // 32768
#define UB_PLANE 18432                  // 128 rows * 144B (64ch fp16 + pad)
#define CMB_SMEM_BYTES (SM_U0 + 2 * UB_PLANE)   // 69632

__global__ __launch_bounds__(CMB_THREADS, 2)
void combine_kernel(const float* __restrict__ bias, float* __restrict__ y) {
    extern __shared__ char smem[];
    int t = threadIdx.x;
    int lane = t & 31, w = t >> 5;
    int ms = w & 3;                 // m-strip: rows ms*32 .. ms*32+31
    int oh = w >> 2;                // o-half: o in [oh*32, oh*32+32)
    int b = blockIdx.y;
    int mBase = blockIdx.x * 128;

    float acc[8][4];                // [mt*4 + oc][frag]
#pragma unroll
    for (int i = 0; i < 8; i++)
#pragma unroll
        for (int e = 0; e < 4; e++) acc[i][e] = 0.f;

    // stage phase p (W 16KB slice + U 32KB tile) into buffer p&1
    auto stage = [&](int p, int buf) {
        const char* wsrc = reinterpret_cast<const char*>(g_wfrag) + (size_t)p * W_SLICE;
        char* wdst = smem + buf * W_SLICE;
#pragma unroll
        for (int jj = 0; jj < 4; jj++) {
            int idx = t + jj * CMB_THREADS;      // 0..1023 x 16B
            cp_async16(smem_u32(wdst + idx * 16), wsrc + idx * 16);
        }
        const char* srcb = reinterpret_cast<const char*>(g_ubf + (size_t)p * UBF_SLOT);
        char* dbase = smem + SM_U0 + buf * UB_PLANE;
#pragma unroll
        for (int jj = 0; jj < 8; jj++) {
            int idx = t + jj * CMB_THREADS;      // 0..2047
            int row = idx >> 4;
            int i   = idx & 15;
            int mm = mBase + row;
            int ok = (mm < MM);
            const char* sp = srcb + (size_t)(ok ? mm : 0) * 256 + b * 128 + i * 8;
            uint32_t d = smem_u32(dbase + row * 144 + i * 8);
            cp_async8(d, sp, ok ? 8 : 0);
        }
    };

    stage(0, 0);
    CP_COMMIT();

    int lr = lane & 7;
    int rsel = (lane & 8) ? 8 : 0;
    int csel = (lane & 16) ? 8 : 0;

#pragma unroll 1
    for (int p = 0; p < KTOT; p++) {
        if (p < KTOT - 1) { stage(p + 1, (p + 1) & 1); CP_COMMIT(); CP_WAIT1(); }
        else              { CP_WAIT0(); }
        __syncthreads();

        const uint4* wb = reinterpret_cast<const uint4*>(smem + (p & 1) * W_SLICE);
        char* ubuf = smem + SM_U0 + (p & 1) * UB_PLANE;
        int row0 = ms * 32 + lr + rsel;          // m-tile 0 ldmatrix row
#pragma unroll
        for (int kl = 0; kl < 4; kl++) {
            int colA = kl * 16 + csel;
            uint32_t a0[4], a1[4];
            ldm_x4(a0, smem_u32(ubuf + row0 * 144 + colA * 2));
            ldm_x4(a1, smem_u32(ubuf + (row0 + 16) * 144 + colA * 2));
#pragma unroll
            for (int oc = 0; oc < 4; oc++) {
                uint4 wv = wb[(kl * 8 + oh * 4 + oc) * 32 + lane]; // LDS.128: wh|wl
                mma16816(acc[oc],     a0, wv.x, wv.y);
                mma16816(acc[oc],     a0, wv.z, wv.w);
                mma16816(acc[4 + oc], a1, wv.x, wv.y);
                mma16816(acc[4 + oc], a1, wv.z, wv.w);
            }
        }
        __syncthreads();
    }

    // epilogue: transpose D through smem (reuse U buffers, 36.8KB >= 33.8KB)
    float* dout = reinterpret_cast<float*>(smem + SM_U0);   // [64][132]
    int g = lane >> 2, tg = lane & 3;
#pragma unroll
    for (int mt = 0; mt < 2; mt++) {
#pragma unroll
        for (int oc = 0; oc < 4; oc++) {
            int o = oh * 32 + oc * 8 + 2 * tg;
            int ml = ms * 32 + mt * 16 + g;
            dout[o * 132 + ml]           = acc[mt * 4 + oc][0];
            dout[(o + 1) * 132 + ml]     = acc[mt * 4 + oc][1];
            dout[o * 132 + ml + 8]       = acc[mt * 4 + oc][2];
            dout[(o + 1) * 132 + ml + 8] = acc[mt * 4 + oc][3];
        }
    }
    __syncthreads();

    int o = t >> 2, q = t & 3;
    float bv = __ldg(bias + o);
    float* yrow = y + ((size_t)b * 64 + o) * MM;
#pragma unroll
    for (int i = 0; i < 8; i++) {
        int c4 = q + i * 4;
        int m = mBase + c4 * 4;
        float4 v = *reinterpret_cast<float4*>(dout + o * 132 + c4 * 4);
        v.x += bv; v.y += bv; v.z += bv; v.w += bv;
        if (m + 3 < MM) {
            *reinterpret_cast<float4*>(yrow + m) = v;
        } else {
            if (m     < MM) yrow[m]     = v.x;
            if (m + 1 < MM) yrow[m + 1] = v.y;
            if (m + 2 < MM) yrow[m + 2] = v.z;
            if (m + 3 < MM) yrow[m + 3] = v.w;
        }
    }
}

// ---------------- launch ------------------------------------------------------
extern "C" void kernel_launch(void* const* d_in, const int* in_sizes, int n_in,
                              void* d_out, int out_size) {
    const int*   LlI  = (const int*)  d_in[0];
    const float* LlV  = (const float*)d_in[1];
    const int*   LuI  = (const int*)  d_in[2];
    const float* LuV  = (const float*)d_in[3];
    const float* x    = (const float*)d_in[4];
    const float* th   = (const float*)d_in[5];
    const float* bias = (const float*)d_in[6];
    float*       y    = (float*)d_out;
    int nnz = in_sizes[1];

    uint16_t* ubf;
    uint4* wfrag;
    cudaGetSymbolAddress((void**)&ubf,   g_ubf);
    cudaGetSymbolAddress((void**)&wfrag, g_wfrag);

    int  *cnt;
    int2 *ents;
    cudaGetSymbolAddress((void**)&cnt,  g_cnt);
    cudaGetSymbolAddress((void**)&ents, g_ents);

    cudaMemsetAsync(cnt, 0, 2 * MM * sizeof(int));

    int eb2 = (2 * nnz + 255) / 256;
    prep_kernel<<<NB_WPREP + NB_TRANS + eb2, 256>>>(
        x, LlI, LuI, LlV, LuV, th, cnt, ents,
        reinterpret_cast<uint2*>(wfrag), nnz);

    uint4* slot0 = reinterpret_cast<uint4*>(ubf);
    uint4* slot1 = reinterpret_cast<uint4*>(ubf + 1 * UBF_SLOT);
    uint4* slot2 = reinterpret_cast<uint4*>(ubf + 2 * UBF_SLOT);
    uint4* slot3 = reinterpret_cast<uint4*>(ubf + 3 * UBF_SLOT);
    uint4* slot4 = reinterpret_cast<uint4*>(ubf + 4 * UBF_SLOT);

    int spmmBlocks = (MM * 32 + 255) / 256;                 // 2 rows per warp
    spmm_dual_kernel<<<spmmBlocks, 256>>>(cnt, ents, slot0, slot0, slot1, slot3);
    spmm_dual_kernel<<<spmmBlocks, 256>>>(cnt, ents, slot1, slot3, slot2, slot4);

    cudaFuncSetAttribute(combine_kernel,
                         cudaFuncAttributeMaxDynamicSharedMemorySize, CMB_SMEM_BYTES);
    combine_kernel<<<dim3((MM + 127) / 128, 2), CMB_THREADS, CMB_SMEM_BYTES>>>(bias, y);
}